// round 15
// baseline (speedup 1.0000x reference)
#include <cuda_runtime.h>
#include <cstdint>

// ---------------- problem constants ----------------
#define Bb 2
#define Ss 2048
#define Hh 1536
#define NHq 12
#define NKVh 4
#define Dd 128
#define Tt (Bb*Ss)          // 4096
#define Ee 8
#define IEXP 512
#define ISH 1024
#define SCALEf 0.0078125f
#define RESMf 0.22f
#define EPSf 1e-6f

typedef unsigned short u16;

// ---------------- bf16 weight copies ----------------
__device__ u16 b_wq   [Hh*Hh];
__device__ u16 b_wk   [NKVh*Dd*Hh];
__device__ u16 b_wv   [NKVh*Dd*Hh];
__device__ u16 b_wo   [Hh*Hh];
__device__ u16 b_shin [2*ISH*Hh];
__device__ u16 b_shout[Hh*ISH];
__device__ u16 b_wg   [Ee*IEXP*Hh];
__device__ u16 b_wu   [Ee*IEXP*Hh];
__device__ u16 b_wd   [Ee*Hh*IEXP];
// ---------------- bf16 activations ----------------
__device__ u16 b_xnorm[Tt*Hh];
__device__ u16 b_q    [Tt*Hh];
__device__ u16 b_k    [Tt*NKVh*Dd];
__device__ u16 b_v    [Tt*NKVh*Dd];
__device__ u16 b_attn [Tt*Hh];
__device__ u16 b_x2   [Tt*Hh];
__device__ u16 b_shg  [Tt*2*ISH];
__device__ u16 b_shh  [Tt*ISH];
__device__ u16 b_gbuf [Ee*Tt*IEXP];
__device__ u16 b_ubuf [Ee*Tt*IEXP];
// ---------------- fp32 scratch ----------------
__device__ float g_hidden[Tt*Hh];
__device__ float g_shared[Tt*Hh];
__device__ float g_ydown [Tt*2*Hh];
__device__ int   g_elist [Ee*Tt];
__device__ int   g_ecount[Ee];
__device__ float g_rwflat[Tt*2];

// ---------------- bf16 helpers ----------------
__device__ __forceinline__ unsigned pk(float lo, float hi)
{
    unsigned r;
    asm("cvt.rn.bf16x2.f32 %0, %1, %2;" : "=r"(r) : "f"(hi), "f"(lo));
    return r;
}
__device__ __forceinline__ u16 f2b(float x) { return (u16)pk(x, x); }
__device__ __forceinline__ float bf2f(u16 u)
{
    return __uint_as_float(((unsigned)u) << 16);
}

#define MMA_BF16(acc, a0,a1,a2,a3, b0,b1) \
    asm volatile( \
        "mma.sync.aligned.m16n8k16.row.col.f32.bf16.bf16.f32 " \
        "{%0,%1,%2,%3}, {%4,%5,%6,%7}, {%8,%9}, {%0,%1,%2,%3};" \
        : "+f"((acc)[0]), "+f"((acc)[1]), "+f"((acc)[2]), "+f"((acc)[3]) \
        : "r"(a0), "r"(a1), "r"(a2), "r"(a3), "r"(b0), "r"(b1))

// ---------------- weight conversion ----------------
__global__ void cvt_bf16(const float* __restrict__ src, u16* __restrict__ dst, int n4)
{
    int i = blockIdx.x*256 + threadIdx.x;
    if (i >= n4) return;
    float4 v = ((const float4*)src)[i];
    uint2 o; o.x = pk(v.x, v.y); o.y = pk(v.z, v.w);
    ((uint2*)dst)[i] = o;
}

// ---------------- GEMM core (bf16 in smem) ----------------
struct SmemT {
    u16 As[2][128][40];
    u16 Bs[2][128][40];
};
#define SMEM_BYTES ((int)sizeof(SmemT))   // 40960

__device__ __forceinline__ void mma_compute(
    const u16 (&A)[128][40], const u16 (&B)[128][40],
    int lane, int wm, int wn, float (&acc)[2][8][4])
{
    const int g = lane >> 2, t2 = (lane & 3)*2;
    #pragma unroll
    for (int kk = 0; kk < 2; kk++) {
        const int kb = kk*16;
        unsigned af[2][4];
        #pragma unroll
        for (int mt = 0; mt < 2; mt++) {
            int ar = wm*32 + mt*16 + g;
            af[mt][0] = *(const unsigned*)&A[ar  ][kb + t2];
            af[mt][1] = *(const unsigned*)&A[ar+8][kb + t2];
            af[mt][2] = *(const unsigned*)&A[ar  ][kb + t2 + 8];
            af[mt][3] = *(const unsigned*)&A[ar+8][kb + t2 + 8];
        }
        #pragma unroll
        for (int nt = 0; nt < 8; nt++) {
            int br = wn*64 + nt*8 + g;
            unsigned b0 = *(const unsigned*)&B[br][kb + t2];
            unsigned b1 = *(const unsigned*)&B[br][kb + t2 + 8];
            #pragma unroll
            for (int mt = 0; mt < 2; mt++)
                MMA_BF16(acc[mt][nt], af[mt][0],af[mt][1],af[mt][2],af[mt][3], b0,b1);
        }
    }
}

// double-buffered K loop on bf16 operands; row = tid>>1, c0off = (tid&1)*16
__device__ __forceinline__ void bf16_db(
    SmemT& S, const u16* ag, const u16* bg,
    int row, int c0off, int K,
    int lane, int wm, int wn, float (&acc)[2][8][4])
{
    const uint4 z = make_uint4(0,0,0,0);
    uint4 a0v = ag ? *(const uint4*)(ag)     : z;
    uint4 a1v = ag ? *(const uint4*)(ag + 8) : z;
    uint4 b0v = *(const uint4*)(bg);
    uint4 b1v = *(const uint4*)(bg + 8);
    *(uint4*)&S.As[0][row][c0off]     = a0v;
    *(uint4*)&S.As[0][row][c0off + 8] = a1v;
    *(uint4*)&S.Bs[0][row][c0off]     = b0v;
    *(uint4*)&S.Bs[0][row][c0off + 8] = b1v;
    __syncthreads();

    int cur = 0;
    for (int k0 = 32; k0 < K; k0 += 32) {
        a0v = ag ? *(const uint4*)(ag + k0)     : z;
        a1v = ag ? *(const uint4*)(ag + k0 + 8) : z;
        b0v = *(const uint4*)(bg + k0);
        b1v = *(const uint4*)(bg + k0 + 8);
        mma_compute(S.As[cur], S.Bs[cur], lane, wm, wn, acc);
        int nxt = cur ^ 1;
        *(uint4*)&S.As[nxt][row][c0off]     = a0v;
        *(uint4*)&S.As[nxt][row][c0off + 8] = a1v;
        *(uint4*)&S.Bs[nxt][row][c0off]     = b0v;
        *(uint4*)&S.Bs[nxt][row][c0off + 8] = b1v;
        __syncthreads();
        cur = nxt;
    }
    mma_compute(S.As[cur], S.Bs[cur], lane, wm, wn, acc);
}

// ---------------- TN GEMM, fp32 output (+res, alpha) ----------------
__global__ void __launch_bounds__(256, 2) tc_gemm_f32(
    const u16* __restrict__ A, int lda,
    const u16* __restrict__ B, int ldb,
    float* __restrict__ C, int ldc,
    int K, float alpha, const float* __restrict__ res)
{
    extern __shared__ char smemraw[];
    SmemT& S = *reinterpret_cast<SmemT*>(smemraw);
    const int tid = threadIdx.x, lane = tid & 31, warp = tid >> 5;
    const int wm = warp & 3, wn = warp >> 2;
    const int m0 = blockIdx.y*128, n0 = blockIdx.x*128;
    const int row = tid >> 1, c0off = (tid & 1)*16;
    const u16* ag = A + (size_t)(m0+row)*lda + c0off;
    const u16* bg = B + (size_t)(n0+row)*ldb + c0off;

    float acc[2][8][4];
    #pragma unroll
    for (int i=0;i<2;i++) for (int j=0;j<8;j++) for (int c=0;c<4;c++) acc[i][j][c]=0.f;

    bf16_db(S, ag, bg, row, c0off, K, lane, wm, wn, acc);

    const int g = lane >> 2, t = lane & 3;
    #pragma unroll
    for (int mt = 0; mt < 2; mt++) {
        int gm = m0 + wm*32 + mt*16 + g;
        #pragma unroll
        for (int nt = 0; nt < 8; nt++) {
            int gn = n0 + wn*64 + nt*8 + t*2;
            float2 v0, v1;
            v0.x = alpha*acc[mt][nt][0]; v0.y = alpha*acc[mt][nt][1];
            v1.x = alpha*acc[mt][nt][2]; v1.y = alpha*acc[mt][nt][3];
            if (res) {
                const float* r0 = res + (size_t)gm*ldc + gn;
                const float* r1 = res + (size_t)(gm+8)*ldc + gn;
                v0.x += r0[0]; v0.y += r0[1];
                v1.x += r1[0]; v1.y += r1[1];
            }
            *(float2*)(C + (size_t)gm*ldc + gn)     = v0;
            *(float2*)(C + (size_t)(gm+8)*ldc + gn) = v1;
        }
    }
}

// ---------------- TN GEMM, bf16 output ----------------
__global__ void __launch_bounds__(256, 2) tc_gemm_bf(
    const u16* __restrict__ A, int lda,
    const u16* __restrict__ B, int ldb,
    u16* __restrict__ C, int ldc, int K)
{
    extern __shared__ char smemraw[];
    SmemT& S = *reinterpret_cast<SmemT*>(smemraw);
    const int tid = threadIdx.x, lane = tid & 31, warp = tid >> 5;
    const int wm = warp & 3, wn = warp >> 2;
    const int m0 = blockIdx.y*128, n0 = blockIdx.x*128;
    const int row = tid >> 1, c0off = (tid & 1)*16;
    const u16* ag = A + (size_t)(m0+row)*lda + c0off;
    const u16* bg = B + (size_t)(n0+row)*ldb + c0off;

    float acc[2][8][4];
    #pragma unroll
    for (int i=0;i<2;i++) for (int j=0;j<8;j++) for (int c=0;c<4;c++) acc[i][j][c]=0.f;

    bf16_db(S, ag, bg, row, c0off, K, lane, wm, wn, acc);

    const int g = lane >> 2, t = lane & 3;
    #pragma unroll
    for (int mt = 0; mt < 2; mt++) {
        int gm = m0 + wm*32 + mt*16 + g;
        #pragma unroll
        for (int nt = 0; nt < 8; nt++) {
            int gn = n0 + wn*64 + nt*8 + t*2;
            *(unsigned*)(C + (size_t)gm*ldc + gn)     = pk(acc[mt][nt][0], acc[mt][nt][1]);
            *(unsigned*)(C + (size_t)(gm+8)*ldc + gn) = pk(acc[mt][nt][2], acc[mt][nt][3]);
        }
    }
}

// ---------------- fused QKV (bf16 out) ----------------
__global__ void __launch_bounds__(256, 2) tc_qkv(
    const u16* __restrict__ A,
    const u16* __restrict__ wq, const u16* __restrict__ wk, const u16* __restrict__ wv,
    u16* __restrict__ q, u16* __restrict__ k, u16* __restrict__ v)
{
    extern __shared__ char smemraw[];
    SmemT& S = *reinterpret_cast<SmemT*>(smemraw);
    const int bx = blockIdx.x;
    const u16* B; u16* C; int ldc, n0;
    if (bx < 12)      { B = wq; C = q; ldc = Hh;      n0 = bx*128; }
    else if (bx < 16) { B = wk; C = k; ldc = NKVh*Dd; n0 = (bx-12)*128; }
    else              { B = wv; C = v; ldc = NKVh*Dd; n0 = (bx-16)*128; }

    const int tid = threadIdx.x, lane = tid & 31, warp = tid >> 5;
    const int wm = warp & 3, wn = warp >> 2;
    const int m0 = blockIdx.y*128;
    const int row = tid >> 1, c0off = (tid & 1)*16;
    const u16* ag = A + (size_t)(m0+row)*Hh + c0off;
    const u16* bg = B + (size_t)(n0+row)*Hh + c0off;

    float acc[2][8][4];
    #pragma unroll
    for (int i=0;i<2;i++) for (int j=0;j<8;j++) for (int c=0;c<4;c++) acc[i][j][c]=0.f;

    bf16_db(S, ag, bg, row, c0off, Hh, lane, wm, wn, acc);

    const int g = lane >> 2, t = lane & 3;
    #pragma unroll
    for (int mt = 0; mt < 2; mt++) {
        int gm = m0 + wm*32 + mt*16 + g;
        #pragma unroll
        for (int nt = 0; nt < 8; nt++) {
            int gn = n0 + wn*64 + nt*8 + t*2;
            *(unsigned*)(C + (size_t)gm*ldc + gn)     = pk(acc[mt][nt][0], acc[mt][nt][1]);
            *(unsigned*)(C + (size_t)(gm+8)*ldc + gn) = pk(acc[mt][nt][2], acc[mt][nt][3]);
        }
    }
}

// ---------------- MoE gate+up (bf16 out, gathered rows) ----------------
__global__ void __launch_bounds__(256, 2) tc_moe_gu(
    const u16* __restrict__ X,
    const u16* __restrict__ w_gate, const u16* __restrict__ w_up,
    u16* __restrict__ gbuf, u16* __restrict__ ubuf)
{
    const int e = blockIdx.z;
    const int count = g_ecount[e];
    const int m0 = blockIdx.y*128;
    if (m0 >= count) return;
    extern __shared__ char smemraw[];
    SmemT& S = *reinterpret_cast<SmemT*>(smemraw);
    __shared__ int rowmap[128];

    const int bx = blockIdx.x;
    const u16* B = (bx < 4 ? w_gate : w_up) + (size_t)e*IEXP*Hh;
    u16* C = (bx < 4 ? gbuf : ubuf);
    const int n0 = (bx & 3)*128;

    const int tid = threadIdx.x, lane = tid & 31, warp = tid >> 5;
    const int wm = warp & 3, wn = warp >> 2;
    const int row = tid >> 1, c0off = (tid & 1)*16;
    if (tid < 128) {
        int r = m0 + tid;
        rowmap[tid] = (r < count) ? (g_elist[e*Tt + r] >> 1) : -1;
    }
    __syncthreads();
    int src = rowmap[row];
    const u16* ag = (src >= 0) ? X + (size_t)src*Hh + c0off : nullptr;
    const u16* bg = B + (size_t)(n0+row)*Hh + c0off;

    float acc[2][8][4];
    #pragma unroll
    for (int i=0;i<2;i++) for (int j=0;j<8;j++) for (int c=0;c<4;c++) acc[i][j][c]=0.f;

    bf16_db(S, ag, bg, row, c0off, Hh, lane, wm, wn, acc);

    const int g = lane >> 2, t = lane & 3;
    #pragma unroll
    for (int mt = 0; mt < 2; mt++) {
        int r0 = m0 + wm*32 + mt*16 + g;
        #pragma unroll
        for (int nt = 0; nt < 8; nt++) {
            int gn = n0 + wn*64 + nt*8 + t*2;
            if (r0 < count)
                *(unsigned*)(C + ((size_t)e*Tt + r0)*IEXP + gn)   = pk(acc[mt][nt][0], acc[mt][nt][1]);
            if (r0+8 < count)
                *(unsigned*)(C + ((size_t)e*Tt + r0+8)*IEXP + gn) = pk(acc[mt][nt][2], acc[mt][nt][3]);
        }
    }
}

// ---------------- MoE down (fp32 scatter out) ----------------
__global__ void __launch_bounds__(256, 2) tc_moe_down(
    const u16* __restrict__ Gact,
    const u16* __restrict__ w_down,
    float* __restrict__ ydown)
{
    const int e = blockIdx.z;
    const int count = g_ecount[e];
    const int m0 = blockIdx.y*128;
    if (m0 >= count) return;
    extern __shared__ char smemraw[];
    SmemT& S = *reinterpret_cast<SmemT*>(smemraw);

    const u16* B = w_down + (size_t)e*Hh*IEXP;
    const int n0 = blockIdx.x*128;
    const int tid = threadIdx.x, lane = tid & 31, warp = tid >> 5;
    const int wm = warp & 3, wn = warp >> 2;
    const int row = tid >> 1, c0off = (tid & 1)*16;
    const u16* ag = Gact + ((size_t)e*Tt + m0 + row)*IEXP + c0off;
    const u16* bg = B + (size_t)(n0+row)*IEXP + c0off;

    float acc[2][8][4];
    #pragma unroll
    for (int i=0;i<2;i++) for (int j=0;j<8;j++) for (int c=0;c<4;c++) acc[i][j][c]=0.f;

    bf16_db(S, ag, bg, row, c0off, IEXP, lane, wm, wn, acc);

    const int* lst = g_elist + e*Tt;
    const int g = lane >> 2, t = lane & 3;
    #pragma unroll
    for (int mt = 0; mt < 2; mt++) {
        int r0 = m0 + wm*32 + mt*16 + g;
        #pragma unroll
        for (int nt = 0; nt < 8; nt++) {
            int gn = n0 + wn*64 + nt*8 + t*2;
            if (r0 < count) {
                float2 v; v.x = acc[mt][nt][0]; v.y = acc[mt][nt][1];
                *(float2*)(ydown + (size_t)lst[r0]*Hh + gn) = v;
            }
            if (r0+8 < count) {
                float2 v; v.x = acc[mt][nt][2]; v.y = acc[mt][nt][3];
                *(float2*)(ydown + (size_t)lst[r0+8]*Hh + gn) = v;
            }
        }
    }
}

// ---------------- bf16 flash attention ----------------
struct AttnSmem {
    u16 Qs[64][136];
    char kvbuf[18432];            // K tile u16[64][136] OR VP unsigned[128][36]
    u16 Ps[64][72];
};
#define ATTN_SMEM ((int)sizeof(AttnSmem))  // 45056

__global__ void __launch_bounds__(128, 2) tc_attn(
    const u16* __restrict__ Q, const u16* __restrict__ Kg,
    const u16* __restrict__ Vg, u16* __restrict__ O)
{
    extern __shared__ char sraw[];
    AttnSmem& S = *reinterpret_cast<AttnSmem*>(sraw);
    u16 (*Ks)[136]      = reinterpret_cast<u16 (*)[136]>(S.kvbuf);
    unsigned (*VP)[36]  = reinterpret_cast<unsigned (*)[36]>(S.kvbuf);

    const int qt = blockIdx.x, h = blockIdx.y, b = blockIdx.z;
    const int kvh = h / (NHq/NKVh);
    const int tid = threadIdx.x, lane = tid & 31, warp = tid >> 5;
    const int g = lane >> 2, t = lane & 3, t2 = t*2;
    const int tq0 = b*Ss + qt*64;
    const int rA = warp*16 + g;

    // load Q tile: raw bf16 copy (scale baked into q by rope)
    #pragma unroll
    for (int i = 0; i < 8; i++) {
        int v = tid + i*128;
        int r = v >> 4, d8 = (v & 15) << 3;
        *(uint4*)&S.Qs[r][d8] = *(const uint4*)(Q + (size_t)(tq0+r)*Hh + h*Dd + d8);
    }

    float o[16][4];
    #pragma unroll
    for (int i = 0; i < 16; i++)
        #pragma unroll
        for (int c = 0; c < 4; c++) o[i][c] = 0.f;
    float m0v = -1e30f, m1v = -1e30f, l0 = 0.f, l1 = 0.f;

    for (int kt = 0; kt <= qt; kt++) {
        const int tk0 = b*Ss + kt*64;
        __syncthreads();
        #pragma unroll
        for (int i = 0; i < 8; i++) {
            int v = tid + i*128;
            int r = v >> 4, d8 = (v & 15) << 3;
            *(uint4*)&Ks[r][d8] = *(const uint4*)(Kg + (size_t)(tk0+r)*(NKVh*Dd) + kvh*Dd + d8);
        }
        __syncthreads();

        float s[8][4];
        #pragma unroll
        for (int nt = 0; nt < 8; nt++)
            #pragma unroll
            for (int c = 0; c < 4; c++) s[nt][c] = 0.f;
        #pragma unroll
        for (int kk = 0; kk < 8; kk++) {
            const int kb = kk*16;
            unsigned a0 = *(const unsigned*)&S.Qs[rA  ][kb + t2];
            unsigned a1 = *(const unsigned*)&S.Qs[rA+8][kb + t2];
            unsigned a2 = *(const unsigned*)&S.Qs[rA  ][kb + t2 + 8];
            unsigned a3 = *(const unsigned*)&S.Qs[rA+8][kb + t2 + 8];
            #pragma unroll
            for (int nt = 0; nt < 8; nt++) {
                unsigned b0 = *(const unsigned*)&Ks[nt*8+g][kb + t2];
                unsigned b1 = *(const unsigned*)&Ks[nt*8+g][kb + t2 + 8];
                MMA_BF16(s[nt], a0,a1,a2,a3, b0,b1);
            }
        }
        if (kt == qt) {
            #pragma unroll
            for (int nt = 0; nt < 8; nt++)
                #pragma unroll
                for (int j = 0; j < 2; j++) {
                    int col = nt*8 + t2 + j;
                    if (col > rA)   s[nt][j]   = -1e30f;
                    if (col > rA+8) s[nt][2+j] = -1e30f;
                }
        }
        float mx0 = -1e30f, mx1 = -1e30f;
        #pragma unroll
        for (int nt = 0; nt < 8; nt++) {
            mx0 = fmaxf(mx0, fmaxf(s[nt][0], s[nt][1]));
            mx1 = fmaxf(mx1, fmaxf(s[nt][2], s[nt][3]));
        }
        mx0 = fmaxf(mx0, __shfl_xor_sync(0xffffffffu, mx0, 1));
        mx0 = fmaxf(mx0, __shfl_xor_sync(0xffffffffu, mx0, 2));
        mx1 = fmaxf(mx1, __shfl_xor_sync(0xffffffffu, mx1, 1));
        mx1 = fmaxf(mx1, __shfl_xor_sync(0xffffffffu, mx1, 2));
        float mn0 = fmaxf(m0v, mx0), mn1 = fmaxf(m1v, mx1);
        float sc0 = __expf(m0v - mn0), sc1 = __expf(m1v - mn1);
        float sum0 = 0.f, sum1 = 0.f;
        #pragma unroll
        for (int nt = 0; nt < 8; nt++) {
            float p0 = __expf(s[nt][0] - mn0);
            float p1 = __expf(s[nt][1] - mn0);
            float p2 = __expf(s[nt][2] - mn1);
            float p3 = __expf(s[nt][3] - mn1);
            sum0 += p0 + p1; sum1 += p2 + p3;
            int c = nt*8 + t2;
            *(unsigned*)&S.Ps[rA  ][c] = pk(p0, p1);
            *(unsigned*)&S.Ps[rA+8][c] = pk(p2, p3);
        }
        sum0 += __shfl_xor_sync(0xffffffffu, sum0, 1);
        sum0 += __shfl_xor_sync(0xffffffffu, sum0, 2);
        sum1 += __shfl_xor_sync(0xffffffffu, sum1, 1);
        sum1 += __shfl_xor_sync(0xffffffffu, sum1, 2);
        l0 = l0*sc0 + sum0; l1 = l1*sc1 + sum1;
        m0v = mn0; m1v = mn1;
        #pragma unroll
        for (int nt = 0; nt < 16; nt++) {
            o[nt][0] *= sc0; o[nt][1] *= sc0;
            o[nt][2] *= sc1; o[nt][3] *= sc1;
        }
        __syncthreads();   // Ps written; K reads done -> reuse kvbuf for VP
        // V pairs: VP[d][p] = {V[2p][d](lo), V[2p+1][d](hi)}
        #pragma unroll
        for (int i = 0; i < 8; i++) {
            int idx = tid + i*128;          // 0..1023
            int p   = idx >> 5;             // kv pair 0..31
            int d2  = (idx & 31) << 1;      // d 0,2,..,62 -> covers via 2 cols
            // each idx handles d2 and d2+64
            const u16* vb0 = Vg + (size_t)(tk0 + 2*p)*(NKVh*Dd) + kvh*Dd;
            const u16* vb1 = vb0 + NKVh*Dd;
            unsigned u0a = *(const unsigned*)(vb0 + d2);
            unsigned u1a = *(const unsigned*)(vb1 + d2);
            VP[d2  ][p] = (u0a & 0xffffu) | (u1a << 16);
            VP[d2+1][p] = (u0a >> 16)     | (u1a & 0xffff0000u);
            unsigned u0b = *(const unsigned*)(vb0 + d2 + 64);
            unsigned u1b = *(const unsigned*)(vb1 + d2 + 64);
            VP[d2+64][p] = (u0b & 0xffffu) | (u1b << 16);
            VP[d2+65][p] = (u0b >> 16)     | (u1b & 0xffff0000u);
        }
        __syncthreads();
        #pragma unroll
        for (int kk = 0; kk < 4; kk++) {
            const int kb = kk*16, kw = kk*8;
            unsigned a0 = *(const unsigned*)&S.Ps[rA  ][kb + t2];
            unsigned a1 = *(const unsigned*)&S.Ps[rA+8][kb + t2];
            unsigned a2 = *(const unsigned*)&S.Ps[rA  ][kb + t2 + 8];
            unsigned a3 = *(const unsigned*)&S.Ps[rA+8][kb + t2 + 8];
            #pragma unroll
            for (int nt = 0; nt < 16; nt++) {
                unsigned b0 = VP[nt*8+g][kw + t];
                unsigned b1 = VP[nt*8+g][kw + t + 4];
                MMA_BF16(o[nt], a0,a1,a2,a3, b0,b1);
            }
        }
    }

    float inv0 = 1.0f / l0, inv1 = 1.0f / l1;
    #pragma unroll
    for (int nt = 0; nt < 16; nt++) {
        int col = nt*8 + t2;
        *(unsigned*)(O + (size_t)(tq0+rA)*Hh   + h*Dd + col) = pk(o[nt][0]*inv0, o[nt][1]*inv0);
        *(unsigned*)(O + (size_t)(tq0+rA+8)*Hh + h*Dd + col) = pk(o[nt][2]*inv1, o[nt][3]*inv1);
    }
}

// ---------------- rmsnorm (fp32 in -> bf16 out) ----------------
__global__ __launch_bounds__(256) void rmsnorm_bf(
    const float* __restrict__ x, const float* __restrict__ w, u16* __restrict__ y)
{
    int t = blockIdx.x;
    const float* xr = x + (size_t)t*Hh;
    float s = 0.f;
    for (int i = threadIdx.x; i < Hh; i += 256) { float v = xr[i]; s += v*v; }
    #pragma unroll
    for (int o = 16; o > 0; o >>= 1) s += __shfl_xor_sync(0xffffffffu, s, o);
    __shared__ float red[8];
    if ((threadIdx.x & 31) == 0) red[threadIdx.x >> 5] = s;
    __syncthreads();
    float tot = 0.f;
    #pragma unroll
    for (int wv = 0; wv < 8; wv++) tot += red[wv];
    float inv = rsqrtf(tot * (1.0f/(float)Hh) + EPSf);
    u16* yr = y + (size_t)t*Hh;
    for (int i = threadIdx.x; i < Hh/2; i += 256) {
        float2 xv = *(const float2*)(xr + 2*i);
        float2 wv2 = *(const float2*)(w + 2*i);
        *(unsigned*)(yr + 2*i) = pk(wv2.x*xv.x*inv, wv2.y*xv.y*inv);
    }
}

// ---------------- RoPE on bf16, with output scale ----------------
__global__ void rope_bf(u16* __restrict__ a, int nheads,
                        const int* __restrict__ pos_ids,
                        const float* __restrict__ cosb,
                        const float* __restrict__ sinb, float oscale)
{
    int idx = blockIdx.x*256 + threadIdx.x;
    int total = Tt * nheads * 64;
    if (idx >= total) return;
    int dd = idx & 63;
    int hh = (idx >> 6) % nheads;
    int t  = idx / (64*nheads);
    int pos = pos_ids[t] & 4095;
    float c1 = cosb[pos*Dd + dd],      s1 = sinb[pos*Dd + dd];
    float c2 = cosb[pos*Dd + dd + 64], s2 = sinb[pos*Dd + dd + 64];
    u16* base = a + (size_t)t*(nheads*Dd) + hh*Dd;
    float x1 = bf2f(base[dd]), x2 = bf2f(base[dd+64]);
    base[dd]    = f2b((x1*c1 - x2*s1)*oscale);
    base[dd+64] = f2b((x2*c2 + x1*s2)*oscale);
}

// ---------------- router (bf16 x) ----------------
__global__ void zero_counts() { if (threadIdx.x < Ee) g_ecount[threadIdx.x] = 0; }

__global__ __launch_bounds__(256) void router_kernel(
    const u16* __restrict__ x, const float* __restrict__ rw)
{
    int t = blockIdx.x;
    const u16* xr = x + (size_t)t*Hh;
    float acc[Ee];
    #pragma unroll
    for (int e = 0; e < Ee; e++) acc[e] = 0.f;
    for (int hh = threadIdx.x; hh < Hh; hh += 256) {
        float xv = bf2f(xr[hh]);
        #pragma unroll
        for (int e = 0; e < Ee; e++) acc[e] += xv * rw[e*Hh + hh];
    }
    #pragma unroll
    for (int e = 0; e < Ee; e++)
        #pragma unroll
        for (int o = 16; o > 0; o >>= 1) acc[e] += __shfl_xor_sync(0xffffffffu, acc[e], o);
    __shared__ float red[8][Ee];
    int warp = threadIdx.x >> 5, lane = threadIdx.x & 31;
    if (lane == 0)
        for (int e = 0; e < Ee; e++) red[warp][e] = acc[e];
    __syncthreads();
    if (threadIdx.x == 0) {
        float l[Ee];
        for (int e = 0; e < Ee; e++) {
            float ssum = 0.f;
            for (int w = 0; w < 8; w++) ssum += red[w][e];
            l[e] = ssum;
        }
        int i1 = 0;
        for (int e = 1; e < Ee; e++) if (l[e] > l[i1]) i1 = e;
        int i2 = -1;
        for (int e = 0; e < Ee; e++) if (e != i1 && (i2 < 0 || l[e] > l[i2])) i2 = e;
        float w1 = 1.f / (1.f + __expf(l[i2] - l[i1]));
        g_rwflat[2*t]   = w1;
        g_rwflat[2*t+1] = 1.f - w1;
        int p1 = atomicAdd(&g_ecount[i1], 1); g_elist[i1*Tt + p1] = 2*t;
        int p2 = atomicAdd(&g_ecount[i2], 1); g_elist[i2*Tt + p2] = 2*t + 1;
    }
}

// ---------------- elementwise (bf16) ----------------
__global__ void swiglu_moe_kernel(u16* __restrict__ gb, const u16* __restrict__ ub)
{
    int w = blockIdx.x*256 + threadIdx.x;     // word index; 2 elems per word
    int e = w >> 20;                           // Tt*IEXP/2 = 2^20 words per expert
    int r = (w >> 8) & 4095;                   // IEXP/2 = 256 words per row
    if (r >= g_ecount[e]) return;
    unsigned gg = ((const unsigned*)gb)[w];
    unsigned uu = ((const unsigned*)ub)[w];
    float g0 = bf2f((u16)gg), g1 = bf2f((u16)(gg >> 16));
    float u0 = bf2f((u16)uu), u1 = bf2f((u16)(uu >> 16));
    float a0 = g0*u0 / (1.f + __expf(-g0));
    float a1 = g1*u1 / (1.f + __expf(-g1));
    ((unsigned*)gb)[w] = pk(a0, a1);
}

__global__ void swiglu_shared_kernel(const u16* __restrict__ shg, u16* __restrict__ sha)
{
    int w = blockIdx.x*256 + threadIdx.x;     // T*ISH/2 words
    int t = w >> 9;                            // ISH/2 = 512 words per row
    int i2 = (w & 511) << 1;
    unsigned av = *(const unsigned*)(shg + (size_t)t*2*ISH + i2);
    unsigned bv = *(const unsigned*)(shg + (size_t)t*2*ISH + ISH + i2);
    float a0 = bf2f((u16)av), a1 = bf2f((u16)(av >> 16));
    float b0 = bf2f((u16)bv), b1 = bf2f((u16)(bv >> 16));
    float r0 = a0*b0 / (1.f + __expf(-a0));
    float r1 = a1*b1 / (1.f + __expf(-a1));
    ((unsigned*)sha)[w] = pk(r0, r1);
}

__global__ void combine_kernel(const float* __restrict__ hid,
                               const float* __restrict__ yd,
                               const float* __restrict__ shr,
                               float* __restrict__ out)
{
    int idx = blockIdx.x*256 + threadIdx.x;
    int t = idx / Hh;
    int c = idx - t*Hh;
    float mo = g_rwflat[2*t]   * yd[(size_t)(2*t)*Hh + c]
             + g_rwflat[2*t+1] * yd[(size_t)(2*t+1)*Hh + c];
    out[idx] = hid[idx] + RESMf * (mo + shr[idx]);
}

// ---------------- launch ----------------
extern "C" void kernel_launch(void* const* d_in, const int* in_sizes, int n_in,
                              void* d_out, int out_size)
{
    const float* hidden    = (const float*)d_in[0];
    const int*   pos       = (const int*)  d_in[1];
    const float* cosb      = (const float*)d_in[2];
    const float* sinb      = (const float*)d_in[3];
    const float* ln1       = (const float*)d_in[4];
    const float* ln2       = (const float*)d_in[5];
    const float* wq        = (const float*)d_in[6];
    const float* wk        = (const float*)d_in[7];
    const float* wv        = (const float*)d_in[8];
    const float* wo        = (const float*)d_in[9];
    const float* router_w  = (const float*)d_in[10];
    const float* w_gate    = (const float*)d_in[11];
    const float* w_up      = (const float*)d_in[12];
    const float* w_down    = (const float*)d_in[13];
    const float* shared_in = (const float*)d_in[14];
    const float* shared_ot = (const float*)d_in[15];
    float* out = (float*)d_out;

    u16 *pb_wq,*pb_wk,*pb_wv,*pb_wo,*pb_shin,*pb_shout,*pb_wg,*pb_wu,*pb_wd;
    u16 *pb_xnorm,*pb_q,*pb_k,*pb_v,*pb_attn,*pb_x2,*pb_shg,*pb_shh,*pb_gbuf,*pb_ubuf;
    float *p_hidden,*p_shared,*p_ydown;
    cudaGetSymbolAddress((void**)&pb_wq, b_wq);
    cudaGetSymbolAddress((void**)&pb_wk, b_wk);
    cudaGetSymbolAddress((void**)&pb_wv, b_wv);
    cudaGetSymbolAddress((void**)&pb_wo, b_wo);
    cudaGetSymbolAddress((void**)&pb_shin, b_shin);
    cudaGetSymbolAddress((void**)&pb_shout, b_shout);
    cudaGetSymbolAddress((void**)&pb_wg, b_wg);
    cudaGetSymbolAddress((void**)&pb_wu, b_wu);
    cudaGetSymbolAddress((void**)&pb_wd, b_wd);
    cudaGetSymbolAddress((void**)&pb_xnorm, b_xnorm);
    cudaGetSymbolAddress((void**)&pb_q, b_q);
    cudaGetSymbolAddress((void**)&pb_k, b_k);
    cudaGetSymbolAddress((void**)&pb_v, b_v);
    cudaGetSymbolAddress((void**)&pb_attn, b_attn);
    cudaGetSymbolAddress((void**)&pb_x2, b_x2);
    cudaGetSymbolAddress((void**)&pb_shg, b_shg);
    cudaGetSymbolAddress((void**)&pb_shh, b_shh);
    cudaGetSymbolAddress((void**)&pb_gbuf, b_gbuf);
    cudaGetSymbolAddress((void**)&pb_ubuf, b_ubuf);
    cudaGetSymbolAddress((void**)&p_hidden, g_hidden);
    cudaGetSymbolAddress((void**)&p_shared, g_shared);
    cudaGetSymbolAddress((void**)&p_ydown,  g_ydown);

    cudaFuncSetAttribute(tc_gemm_f32,  cudaFuncAttributeMaxDynamicSharedMemorySize, SMEM_BYTES);
    cudaFuncSetAttribute(tc_gemm_bf,   cudaFuncAttributeMaxDynamicSharedMemorySize, SMEM_BYTES);
    cudaFuncSetAttribute(tc_qkv,       cudaFuncAttributeMaxDynamicSharedMemorySize, SMEM_BYTES);
    cudaFuncSetAttribute(tc_moe_gu,    cudaFuncAttributeMaxDynamicSharedMemorySize, SMEM_BYTES);
    cudaFuncSetAttribute(tc_moe_down,  cudaFuncAttributeMaxDynamicSharedMemorySize, SMEM_BYTES);
    cudaFuncSetAttribute(tc_attn,      cudaFuncAttributeMaxDynamicSharedMemorySize, ATTN_SMEM);

    // ---- weight conversion (graph-replayed; ~30us) ----
    #define CV(src, dst, n) cvt_bf16<<<((n)/4 + 255)/256, 256>>>((src), (dst), (n)/4)
    CV(wq, pb_wq, Hh*Hh);
    CV(wk, pb_wk, NKVh*Dd*Hh);
    CV(wv, pb_wv, NKVh*Dd*Hh);
    CV(wo, pb_wo, Hh*Hh);
    CV(shared_in, pb_shin, 2*ISH*Hh);
    CV(shared_ot, pb_shout, Hh*ISH);
    CV(w_gate, pb_wg, Ee*IEXP*Hh);
    CV(w_up,   pb_wu, Ee*IEXP*Hh);
    CV(w_down, pb_wd, Ee*Hh*IEXP);
    #undef CV

    // ---- attention block ----
    rmsnorm_bf<<<Tt, 256>>>(hidden, ln1, pb_xnorm);
    tc_qkv<<<dim3(20,32), 256, SMEM_BYTES>>>(pb_xnorm, pb_wq, pb_wk, pb_wv, pb_q, pb_k, pb_v);
    rope_bf<<<(Tt*NHq*64 + 255)/256, 256>>>(pb_q, NHq, pos, cosb, sinb, SCALEf);
    rope_bf<<<(Tt*NKVh*64 + 255)/256, 256>>>(pb_k, NKVh, pos, cosb, sinb, 1.f);
    tc_attn<<<dim3(Ss/64, NHq, Bb), 128, ATTN_SMEM>>>(pb_q, pb_k, pb_v, pb_attn);
    tc_gemm_f32<<<dim3(12,32), 256, SMEM_BYTES>>>(pb_attn, Hh, pb_wo, Hh, p_hidden, Hh, Hh, RESMf, hidden);

    // ---- MoE + shared MLP block ----
    rmsnorm_bf<<<Tt, 256>>>(p_hidden, ln2, pb_x2);
    zero_counts<<<1, 32>>>();
    router_kernel<<<Tt, 256>>>(pb_x2, router_w);
    tc_gemm_bf<<<dim3(16,32), 256, SMEM_BYTES>>>(pb_x2, Hh, pb_shin, Hh, pb_shg, 2*ISH, Hh);
    tc_moe_gu<<<dim3(8,32,Ee), 256, SMEM_BYTES>>>(pb_x2, pb_wg, pb_wu, pb_gbuf, pb_ubuf);
    swiglu_moe_kernel<<<(Ee*Tt*IEXP/2)/256, 256>>>(pb_gbuf, pb_ubuf);
    tc_moe_down<<<dim3(12,32,Ee), 256, SMEM_BYTES>>>(pb_gbuf, pb_wd, p_ydown);
    swiglu_shared_kernel<<<(Tt*ISH/2)/256, 256>>>(pb_shg, pb_shh);
    tc_gemm_f32<<<dim3(12,32), 256, SMEM_BYTES>>>(pb_shh, ISH, pb_shout, ISH, p_shared, Hh, ISH, 1.f, nullptr);
    combine_kernel<<<(Tt*Hh)/256, 256>>>(p_hidden, p_ydown, p_shared, out);
}

// round 16
// speedup vs baseline: 1.3025x; 1.3025x over previous
#include <cuda_runtime.h>
#include <cstdint>

// ---------------- problem constants ----------------
#define Bb 2
#define Ss 2048
#define Hh 1536
#define NHq 12
#define NKVh 4
#define Dd 128
#define Tt (Bb*Ss)          // 4096
#define Ee 8
#define IEXP 512
#define ISH 1024
#define SCALEf 0.0078125f
#define RESMf 0.22f
#define EPSf 1e-6f

typedef unsigned short u16;

// ---------------- scratch ----------------
__device__ float g_xnorm [Tt*Hh];
__device__ float g_q     [Tt*Hh];
__device__ float g_k     [Tt*NKVh*Dd];
__device__ float g_v     [Tt*NKVh*Dd];
__device__ float g_attn  [Tt*Hh];
__device__ float g_hidden[Tt*Hh];
__device__ float g_x2    [Tt*Hh];
__device__ float g_shgate[Tt*2*ISH];
__device__ float g_shh   [Tt*ISH];
__device__ float g_shared[Tt*Hh];
__device__ float g_gbuf  [Ee*Tt*IEXP];
__device__ float g_ubuf  [Ee*Tt*IEXP];
__device__ float g_ydown [Tt*2*Hh];
__device__ int   g_elist [Ee*Tt];
__device__ int   g_ecount[Ee];
__device__ float g_rwflat[Tt*2];
// bf16 weight copies (converted once per launch, graph-replayed)
__device__ u16 b_wq   [Hh*Hh];
__device__ u16 b_wk   [NKVh*Dd*Hh];
__device__ u16 b_wv   [NKVh*Dd*Hh];
__device__ u16 b_wo   [Hh*Hh];
__device__ u16 b_shin [2*ISH*Hh];
__device__ u16 b_shout[Hh*ISH];
__device__ u16 b_wg   [Ee*IEXP*Hh];
__device__ u16 b_wu   [Ee*IEXP*Hh];
__device__ u16 b_wd   [Ee*Hh*IEXP];

// ---------------- bf16 helpers ----------------
__device__ __forceinline__ unsigned pk(float lo, float hi)
{
    unsigned r;
    asm("cvt.rn.bf16x2.f32 %0, %1, %2;" : "=r"(r) : "f"(hi), "f"(lo));
    return r;
}

#define MMA_BF16(acc, a0,a1,a2,a3, b0,b1) \
    asm volatile( \
        "mma.sync.aligned.m16n8k16.row.col.f32.bf16.bf16.f32 " \
        "{%0,%1,%2,%3}, {%4,%5,%6,%7}, {%8,%9}, {%0,%1,%2,%3};" \
        : "+f"((acc)[0]), "+f"((acc)[1]), "+f"((acc)[2]), "+f"((acc)[3]) \
        : "r"(a0), "r"(a1), "r"(a2), "r"(a3), "r"(b0), "r"(b1))

// ---------------- weight conversion ----------------
__global__ void cvt_bf16(const float* __restrict__ src, u16* __restrict__ dst, int n4)
{
    int i = blockIdx.x*256 + threadIdx.x;
    if (i >= n4) return;
    float4 v = ((const float4*)src)[i];
    uint2 o; o.x = pk(v.x, v.y); o.y = pk(v.z, v.w);
    ((uint2*)dst)[i] = o;
}

// ---------------- GEMM core (bf16 in smem; A fp32-staged, B raw bf16) ----------------
struct SmemT {
    u16 As[2][128][40];
    u16 Bs[2][128][40];
};
#define SMEM_BYTES ((int)sizeof(SmemT))   // 40960

__device__ __forceinline__ void mma_compute(
    const u16 (&A)[128][40], const u16 (&B)[128][40],
    int lane, int wm, int wn, float (&acc)[2][8][4])
{
    const int g = lane >> 2, t2 = (lane & 3)*2;
    #pragma unroll
    for (int kk = 0; kk < 2; kk++) {
        const int kb = kk*16;
        unsigned af[2][4];
        #pragma unroll
        for (int mt = 0; mt < 2; mt++) {
            int ar = wm*32 + mt*16 + g;
            af[mt][0] = *(const unsigned*)&A[ar  ][kb + t2];
            af[mt][1] = *(const unsigned*)&A[ar+8][kb + t2];
            af[mt][2] = *(const unsigned*)&A[ar  ][kb + t2 + 8];
            af[mt][3] = *(const unsigned*)&A[ar+8][kb + t2 + 8];
        }
        #pragma unroll
        for (int nt = 0; nt < 8; nt++) {
            int br = wn*64 + nt*8 + g;
            unsigned b0 = *(const unsigned*)&B[br][kb + t2];
            unsigned b1 = *(const unsigned*)&B[br][kb + t2 + 8];
            #pragma unroll
            for (int mt = 0; mt < 2; mt++)
                MMA_BF16(acc[mt][nt], af[mt][0],af[mt][1],af[mt][2],af[mt][3], b0,b1);
        }
    }
}

// double-buffered K loop; A fp32 (cvt at staging), B bf16 (raw copy).
// row = tid>>1, c0off = (tid&1)*16 (elements)
__device__ __forceinline__ void mix_db(
    SmemT& S, const float* ag, const u16* bg,
    int row, int c0off, int K,
    int lane, int wm, int wn, float (&acc)[2][8][4])
{
    const uint4 zu = make_uint4(0,0,0,0);
    float4 a0v = ag ? *(const float4*)(ag)      : make_float4(0,0,0,0);
    float4 a1v = ag ? *(const float4*)(ag + 4)  : make_float4(0,0,0,0);
    float4 a2v = ag ? *(const float4*)(ag + 8)  : make_float4(0,0,0,0);
    float4 a3v = ag ? *(const float4*)(ag + 12) : make_float4(0,0,0,0);
    uint4  b0v = *(const uint4*)(bg);
    uint4  b1v = *(const uint4*)(bg + 8);
    uint4 ap0, ap1;
    ap0.x = pk(a0v.x, a0v.y); ap0.y = pk(a0v.z, a0v.w);
    ap0.z = pk(a1v.x, a1v.y); ap0.w = pk(a1v.z, a1v.w);
    ap1.x = pk(a2v.x, a2v.y); ap1.y = pk(a2v.z, a2v.w);
    ap1.z = pk(a3v.x, a3v.y); ap1.w = pk(a3v.z, a3v.w);
    *(uint4*)&S.As[0][row][c0off]     = ap0;
    *(uint4*)&S.As[0][row][c0off + 8] = ap1;
    *(uint4*)&S.Bs[0][row][c0off]     = b0v;
    *(uint4*)&S.Bs[0][row][c0off + 8] = b1v;
    __syncthreads();

    int cur = 0;
    for (int k0 = 32; k0 < K; k0 += 32) {
        a0v = ag ? *(const float4*)(ag + k0)      : make_float4(0,0,0,0);
        a1v = ag ? *(const float4*)(ag + k0 + 4)  : make_float4(0,0,0,0);
        a2v = ag ? *(const float4*)(ag + k0 + 8)  : make_float4(0,0,0,0);
        a3v = ag ? *(const float4*)(ag + k0 + 12) : make_float4(0,0,0,0);
        b0v = *(const uint4*)(bg + k0);
        b1v = *(const uint4*)(bg + k0 + 8);
        mma_compute(S.As[cur], S.Bs[cur], lane, wm, wn, acc);
        int nxt = cur ^ 1;
        ap0.x = pk(a0v.x, a0v.y); ap0.y = pk(a0v.z, a0v.w);
        ap0.z = pk(a1v.x, a1v.y); ap0.w = pk(a1v.z, a1v.w);
        ap1.x = pk(a2v.x, a2v.y); ap1.y = pk(a2v.z, a2v.w);
        ap1.z = pk(a3v.x, a3v.y); ap1.w = pk(a3v.z, a3v.w);
        *(uint4*)&S.As[nxt][row][c0off]     = ap0;
        *(uint4*)&S.As[nxt][row][c0off + 8] = ap1;
        *(uint4*)&S.Bs[nxt][row][c0off]     = b0v;
        *(uint4*)&S.Bs[nxt][row][c0off + 8] = b1v;
        __syncthreads();
        cur = nxt;
    }
    mma_compute(S.As[cur], S.Bs[cur], lane, wm, wn, acc);
    (void)zu;
}

// ---------------- generic TN GEMM ----------------
__global__ void __launch_bounds__(256, 2) tc_gemm(
    const float* __restrict__ A, int lda,
    const u16* __restrict__ B, int ldb,
    float* __restrict__ C, int ldc,
    int K, float alpha, const float* __restrict__ res)
{
    extern __shared__ char smemraw[];
    SmemT& S = *reinterpret_cast<SmemT*>(smemraw);
    const int tid = threadIdx.x, lane = tid & 31, warp = tid >> 5;
    const int wm = warp & 3, wn = warp >> 2;
    const int m0 = blockIdx.y*128, n0 = blockIdx.x*128;
    const int row = tid >> 1, c0off = (tid & 1)*16;
    const float* ag = A + (size_t)(m0+row)*lda + c0off;
    const u16*   bg = B + (size_t)(n0+row)*ldb + c0off;

    float acc[2][8][4];
    #pragma unroll
    for (int i=0;i<2;i++) for (int j=0;j<8;j++) for (int c=0;c<4;c++) acc[i][j][c]=0.f;

    mix_db(S, ag, bg, row, c0off, K, lane, wm, wn, acc);

    const int g = lane >> 2, t = lane & 3;
    #pragma unroll
    for (int mt = 0; mt < 2; mt++) {
        int gm = m0 + wm*32 + mt*16 + g;
        #pragma unroll
        for (int nt = 0; nt < 8; nt++) {
            int gn = n0 + wn*64 + nt*8 + t*2;
            float2 v0, v1;
            v0.x = alpha*acc[mt][nt][0]; v0.y = alpha*acc[mt][nt][1];
            v1.x = alpha*acc[mt][nt][2]; v1.y = alpha*acc[mt][nt][3];
            if (res) {
                const float* r0 = res + (size_t)gm*ldc + gn;
                const float* r1 = res + (size_t)(gm+8)*ldc + gn;
                v0.x += r0[0]; v0.y += r0[1];
                v1.x += r1[0]; v1.y += r1[1];
            }
            *(float2*)(C + (size_t)gm*ldc + gn)     = v0;
            *(float2*)(C + (size_t)(gm+8)*ldc + gn) = v1;
        }
    }
}

// ---------------- fused QKV ----------------
__global__ void __launch_bounds__(256, 2) tc_qkv(
    const float* __restrict__ A,
    const u16* __restrict__ wq, const u16* __restrict__ wk, const u16* __restrict__ wv,
    float* __restrict__ q, float* __restrict__ k, float* __restrict__ v)
{
    extern __shared__ char smemraw[];
    SmemT& S = *reinterpret_cast<SmemT*>(smemraw);
    const int bx = blockIdx.x;
    const u16* B; float* C; int ldc, n0;
    if (bx < 12)      { B = wq; C = q; ldc = Hh;      n0 = bx*128; }
    else if (bx < 16) { B = wk; C = k; ldc = NKVh*Dd; n0 = (bx-12)*128; }
    else              { B = wv; C = v; ldc = NKVh*Dd; n0 = (bx-16)*128; }

    const int tid = threadIdx.x, lane = tid & 31, warp = tid >> 5;
    const int wm = warp & 3, wn = warp >> 2;
    const int m0 = blockIdx.y*128;
    const int row = tid >> 1, c0off = (tid & 1)*16;
    const float* ag = A + (size_t)(m0+row)*Hh + c0off;
    const u16*   bg = B + (size_t)(n0+row)*Hh + c0off;

    float acc[2][8][4];
    #pragma unroll
    for (int i=0;i<2;i++) for (int j=0;j<8;j++) for (int c=0;c<4;c++) acc[i][j][c]=0.f;

    mix_db(S, ag, bg, row, c0off, Hh, lane, wm, wn, acc);

    const int g = lane >> 2, t = lane & 3;
    #pragma unroll
    for (int mt = 0; mt < 2; mt++) {
        int gm = m0 + wm*32 + mt*16 + g;
        #pragma unroll
        for (int nt = 0; nt < 8; nt++) {
            int gn = n0 + wn*64 + nt*8 + t*2;
            float2 v0, v1;
            v0.x = acc[mt][nt][0]; v0.y = acc[mt][nt][1];
            v1.x = acc[mt][nt][2]; v1.y = acc[mt][nt][3];
            *(float2*)(C + (size_t)gm*ldc + gn)     = v0;
            *(float2*)(C + (size_t)(gm+8)*ldc + gn) = v1;
        }
    }
}

// ---------------- MoE gate+up (gathered rows) ----------------
__global__ void __launch_bounds__(256, 2) tc_moe_gu(
    const float* __restrict__ X,
    const u16* __restrict__ w_gate, const u16* __restrict__ w_up,
    float* __restrict__ gbuf, float* __restrict__ ubuf)
{
    const int e = blockIdx.z;
    const int count = g_ecount[e];
    const int m0 = blockIdx.y*128;
    if (m0 >= count) return;
    extern __shared__ char smemraw[];
    SmemT& S = *reinterpret_cast<SmemT*>(smemraw);
    __shared__ int rowmap[128];

    const int bx = blockIdx.x;
    const u16* B = (bx < 4 ? w_gate : w_up) + (size_t)e*IEXP*Hh;
    float* C = (bx < 4 ? gbuf : ubuf);
    const int n0 = (bx & 3)*128;

    const int tid = threadIdx.x, lane = tid & 31, warp = tid >> 5;
    const int wm = warp & 3, wn = warp >> 2;
    const int row = tid >> 1, c0off = (tid & 1)*16;
    if (tid < 128) {
        int r = m0 + tid;
        rowmap[tid] = (r < count) ? (g_elist[e*Tt + r] >> 1) : -1;
    }
    __syncthreads();
    int src = rowmap[row];
    const float* ag = (src >= 0) ? X + (size_t)src*Hh + c0off : nullptr;
    const u16*   bg = B + (size_t)(n0+row)*Hh + c0off;

    float acc[2][8][4];
    #pragma unroll
    for (int i=0;i<2;i++) for (int j=0;j<8;j++) for (int c=0;c<4;c++) acc[i][j][c]=0.f;

    mix_db(S, ag, bg, row, c0off, Hh, lane, wm, wn, acc);

    const int g = lane >> 2, t = lane & 3;
    #pragma unroll
    for (int mt = 0; mt < 2; mt++) {
        int r0 = m0 + wm*32 + mt*16 + g;
        #pragma unroll
        for (int nt = 0; nt < 8; nt++) {
            int gn = n0 + wn*64 + nt*8 + t*2;
            if (r0 < count) {
                float2 v; v.x = acc[mt][nt][0]; v.y = acc[mt][nt][1];
                *(float2*)(C + ((size_t)e*Tt + r0)*IEXP + gn) = v;
            }
            if (r0+8 < count) {
                float2 v; v.x = acc[mt][nt][2]; v.y = acc[mt][nt][3];
                *(float2*)(C + ((size_t)e*Tt + r0+8)*IEXP + gn) = v;
            }
        }
    }
}

// ---------------- MoE down (scatter rows) ----------------
__global__ void __launch_bounds__(256, 2) tc_moe_down(
    const float* __restrict__ Gact,
    const u16* __restrict__ w_down,
    float* __restrict__ ydown)
{
    const int e = blockIdx.z;
    const int count = g_ecount[e];
    const int m0 = blockIdx.y*128;
    if (m0 >= count) return;
    extern __shared__ char smemraw[];
    SmemT& S = *reinterpret_cast<SmemT*>(smemraw);

    const u16* B = w_down + (size_t)e*Hh*IEXP;
    const int n0 = blockIdx.x*128;
    const int tid = threadIdx.x, lane = tid & 31, warp = tid >> 5;
    const int wm = warp & 3, wn = warp >> 2;
    const int row = tid >> 1, c0off = (tid & 1)*16;
    const float* ag = Gact + ((size_t)e*Tt + m0 + row)*IEXP + c0off;
    const u16*   bg = B + (size_t)(n0+row)*IEXP + c0off;

    float acc[2][8][4];
    #pragma unroll
    for (int i=0;i<2;i++) for (int j=0;j<8;j++) for (int c=0;c<4;c++) acc[i][j][c]=0.f;

    mix_db(S, ag, bg, row, c0off, IEXP, lane, wm, wn, acc);

    const int* lst = g_elist + e*Tt;
    const int g = lane >> 2, t = lane & 3;
    #pragma unroll
    for (int mt = 0; mt < 2; mt++) {
        int r0 = m0 + wm*32 + mt*16 + g;
        #pragma unroll
        for (int nt = 0; nt < 8; nt++) {
            int gn = n0 + wn*64 + nt*8 + t*2;
            if (r0 < count) {
                float2 v; v.x = acc[mt][nt][0]; v.y = acc[mt][nt][1];
                *(float2*)(ydown + (size_t)lst[r0]*Hh + gn) = v;
            }
            if (r0+8 < count) {
                float2 v; v.x = acc[mt][nt][2]; v.y = acc[mt][nt][3];
                *(float2*)(ydown + (size_t)lst[r0+8]*Hh + gn) = v;
            }
        }
    }
}

// ---------------- bf16 flash attention (round-14 proven version) ----------------
struct AttnSmem {
    u16 Qs[64][136];
    char kvbuf[18432];            // K tile u16[64][136] OR VP unsigned[128][36]
    u16 Ps[64][72];
};
#define ATTN_SMEM ((int)sizeof(AttnSmem))  // 45056

__global__ void __launch_bounds__(128, 2) tc_attn(
    const float* __restrict__ Q, const float* __restrict__ Kg,
    const float* __restrict__ Vg, float* __restrict__ O)
{
    extern __shared__ char sraw[];
    AttnSmem& S = *reinterpret_cast<AttnSmem*>(sraw);
    u16 (*Ks)[136]      = reinterpret_cast<u16 (*)[136]>(S.kvbuf);
    unsigned (*VP)[36]  = reinterpret_cast<unsigned (*)[36]>(S.kvbuf);

    const int qt = blockIdx.x, h = blockIdx.y, b = blockIdx.z;
    const int kvh = h / (NHq/NKVh);
    const int tid = threadIdx.x, lane = tid & 31, warp = tid >> 5;
    const int g = lane >> 2, t = lane & 3, t2 = t*2;
    const int tq0 = b*Ss + qt*64;
    const int rA = warp*16 + g;

    #pragma unroll
    for (int i = 0; i < 16; i++) {
        int v = tid + i*128;
        int r = v >> 5, dq = (v & 31) << 2;
        float4 qv = *(const float4*)(Q + (size_t)(tq0+r)*Hh + h*Dd + dq);
        *(unsigned*)&S.Qs[r][dq]   = pk(qv.x*SCALEf, qv.y*SCALEf);
        *(unsigned*)&S.Qs[r][dq+2] = pk(qv.z*SCALEf, qv.w*SCALEf);
    }

    float o[16][4];
    #pragma unroll
    for (int i = 0; i < 16; i++)
        #pragma unroll
        for (int c = 0; c < 4; c++) o[i][c] = 0.f;
    float m0v = -1e30f, m1v = -1e30f, l0 = 0.f, l1 = 0.f;

    for (int kt = 0; kt <= qt; kt++) {
        const int tk0 = b*Ss + kt*64;
        __syncthreads();
        #pragma unroll
        for (int i = 0; i < 16; i++) {
            int v = tid + i*128;
            int r = v >> 5, dq = (v & 31) << 2;
            float4 kv = *(const float4*)(Kg + (size_t)(tk0+r)*(NKVh*Dd) + kvh*Dd + dq);
            *(unsigned*)&Ks[r][dq]   = pk(kv.x, kv.y);
            *(unsigned*)&Ks[r][dq+2] = pk(kv.z, kv.w);
        }
        __syncthreads();

        float s[8][4];
        #pragma unroll
        for (int nt = 0; nt < 8; nt++)
            #pragma unroll
            for (int c = 0; c < 4; c++) s[nt][c] = 0.f;
        #pragma unroll
        for (int kk = 0; kk < 8; kk++) {
            const int kb = kk*16;
            unsigned a0 = *(const unsigned*)&S.Qs[rA  ][kb + t2];
            unsigned a1 = *(const unsigned*)&S.Qs[rA+8][kb + t2];
            unsigned a2 = *(const unsigned*)&S.Qs[rA  ][kb + t2 + 8];
            unsigned a3 = *(const unsigned*)&S.Qs[rA+8][kb + t2 + 8];
            #pragma unroll
            for (int nt = 0; nt < 8; nt++) {
                unsigned b0 = *(const unsigned*)&Ks[nt*8+g][kb + t2];
                unsigned b1 = *(const unsigned*)&Ks[nt*8+g][kb + t2 + 8];
                MMA_BF16(s[nt], a0,a1,a2,a3, b0,b1);
            }
        }
        if (kt == qt) {
            #pragma unroll
            for (int nt = 0; nt < 8; nt++)
                #pragma unroll
                for (int j = 0; j < 2; j++) {
                    int col = nt*8 + t2 + j;
                    if (col > rA)   s[nt][j]   = -1e30f;
                    if (col > rA+8) s[nt][2+j] = -1e30f;
                }
        }
        float mx0 = -1e30f, mx1 = -1e30f;
        #pragma unroll
        for (int nt = 0; nt < 8; nt++) {
            mx0 = fmaxf(mx0, fmaxf(s[nt][0], s[nt][1]));
            mx1 = fmaxf(mx1, fmaxf(s[nt][2], s[nt][3]));
        }
        mx0 = fmaxf(mx0, __shfl_xor_sync(0xffffffffu, mx0, 1));
        mx0 = fmaxf(mx0, __shfl_xor_sync(0xffffffffu, mx0, 2));
        mx1 = fmaxf(mx1, __shfl_xor_sync(0xffffffffu, mx1, 1));
        mx1 = fmaxf(mx1, __shfl_xor_sync(0xffffffffu, mx1, 2));
        float mn0 = fmaxf(m0v, mx0), mn1 = fmaxf(m1v, mx1);
        float sc0 = __expf(m0v - mn0), sc1 = __expf(m1v - mn1);
        float sum0 = 0.f, sum1 = 0.f;
        #pragma unroll
        for (int nt = 0; nt < 8; nt++) {
            float p0 = __expf(s[nt][0] - mn0);
            float p1 = __expf(s[nt][1] - mn0);
            float p2 = __expf(s[nt][2] - mn1);
            float p3 = __expf(s[nt][3] - mn1);
            sum0 += p0 + p1; sum1 += p2 + p3;
            int c = nt*8 + t2;
            *(unsigned*)&S.Ps[rA  ][c] = pk(p0, p1);
            *(unsigned*)&S.Ps[rA+8][c] = pk(p2, p3);
        }
        sum0 += __shfl_xor_sync(0xffffffffu, sum0, 1);
        sum0 += __shfl_xor_sync(0xffffffffu, sum0, 2);
        sum1 += __shfl_xor_sync(0xffffffffu, sum1, 1);
        sum1 += __shfl_xor_sync(0xffffffffu, sum1, 2);
        l0 = l0*sc0 + sum0; l1 = l1*sc1 + sum1;
        m0v = mn0; m1v = mn1;
        #pragma unroll
        for (int nt = 0; nt < 16; nt++) {
            o[nt][0] *= sc0; o[nt][1] *= sc0;
            o[nt][2] *= sc1; o[nt][3] *= sc1;
        }
        __syncthreads();
        #pragma unroll
        for (int i = 0; i < 16; i++) {
            int idx = tid + i*128;
            int p   = idx >> 6;
            int d2  = (idx & 63) << 1;
            const float* vb = Vg + (size_t)(tk0 + 2*p)*(NKVh*Dd) + kvh*Dd + d2;
            float2 r0 = *(const float2*)(vb);
            float2 r1 = *(const float2*)(vb + NKVh*Dd);
            VP[d2  ][p] = pk(r0.x, r1.x);
            VP[d2+1][p] = pk(r0.y, r1.y);
        }
        __syncthreads();
        #pragma unroll
        for (int kk = 0; kk < 4; kk++) {
            const int kb = kk*16, kw = kk*8;
            unsigned a0 = *(const unsigned*)&S.Ps[rA  ][kb + t2];
            unsigned a1 = *(const unsigned*)&S.Ps[rA+8][kb + t2];
            unsigned a2 = *(const unsigned*)&S.Ps[rA  ][kb + t2 + 8];
            unsigned a3 = *(const unsigned*)&S.Ps[rA+8][kb + t2 + 8];
            #pragma unroll
            for (int nt = 0; nt < 16; nt++) {
                unsigned b0 = VP[nt*8+g][kw + t];
                unsigned b1 = VP[nt*8+g][kw + t + 4];
                MMA_BF16(o[nt], a0,a1,a2,a3, b0,b1);
            }
        }
    }

    float inv0 = 1.0f / l0, inv1 = 1.0f / l1;
    #pragma unroll
    for (int nt = 0; nt < 16; nt++) {
        int col = nt*8 + t2;
        float2 v0, v1;
        v0.x = o[nt][0]*inv0; v0.y = o[nt][1]*inv0;
        v1.x = o[nt][2]*inv1; v1.y = o[nt][3]*inv1;
        *(float2*)(O + (size_t)(tq0+rA)*Hh   + h*Dd + col) = v0;
        *(float2*)(O + (size_t)(tq0+rA+8)*Hh + h*Dd + col) = v1;
    }
}

// ---------------- rmsnorm ----------------
__global__ __launch_bounds__(256) void rmsnorm_kernel(
    const float* __restrict__ x, const float* __restrict__ w, float* __restrict__ y)
{
    int t = blockIdx.x;
    const float* xr = x + (size_t)t*Hh;
    float s = 0.f;
    for (int i = threadIdx.x; i < Hh; i += 256) { float v = xr[i]; s += v*v; }
    #pragma unroll
    for (int o = 16; o > 0; o >>= 1) s += __shfl_xor_sync(0xffffffffu, s, o);
    __shared__ float red[8];
    if ((threadIdx.x & 31) == 0) red[threadIdx.x >> 5] = s;
    __syncthreads();
    float tot = 0.f;
    #pragma unroll
    for (int wv = 0; wv < 8; wv++) tot += red[wv];
    float inv = rsqrtf(tot * (1.0f/(float)Hh) + EPSf);
    float* yr = y + (size_t)t*Hh;
    for (int i = threadIdx.x; i < Hh; i += 256) yr[i] = w[i]*xr[i]*inv;
}

// ---------------- RoPE ----------------
__global__ void rope_kernel(float* __restrict__ a, int nheads,
                            const int* __restrict__ pos_ids,
                            const float* __restrict__ cosb,
                            const float* __restrict__ sinb)
{
    int idx = blockIdx.x*256 + threadIdx.x;
    int total = Tt * nheads * 64;
    if (idx >= total) return;
    int dd = idx & 63;
    int hh = (idx >> 6) % nheads;
    int t  = idx / (64*nheads);
    int pos = pos_ids[t] & 4095;
    float c1 = cosb[pos*Dd + dd],      s1 = sinb[pos*Dd + dd];
    float c2 = cosb[pos*Dd + dd + 64], s2 = sinb[pos*Dd + dd + 64];
    float* base = a + (size_t)t*(nheads*Dd) + hh*Dd;
    float x1 = base[dd], x2 = base[dd+64];
    base[dd]     = x1*c1 - x2*s1;
    base[dd+64]  = x2*c2 + x1*s2;
}

// ---------------- router ----------------
__global__ void zero_counts() { if (threadIdx.x < Ee) g_ecount[threadIdx.x] = 0; }

__global__ __launch_bounds__(256) void router_kernel(
    const float* __restrict__ x, const float* __restrict__ rw)
{
    int t = blockIdx.x;
    const float* xr = x + (size_t)t*Hh;
    float acc[Ee];
    #pragma unroll
    for (int e = 0; e < Ee; e++) acc[e] = 0.f;
    for (int hh = threadIdx.x; hh < Hh; hh += 256) {
        float xv = xr[hh];
        #pragma unroll
        for (int e = 0; e < Ee; e++) acc[e] += xv * rw[e*Hh + hh];
    }
    #pragma unroll
    for (int e = 0; e < Ee; e++)
        #pragma unroll
        for (int o = 16; o > 0; o >>= 1) acc[e] += __shfl_xor_sync(0xffffffffu, acc[e], o);
    __shared__ float red[8][Ee];
    int warp = threadIdx.x >> 5, lane = threadIdx.x & 31;
    if (lane == 0)
        for (int e = 0; e < Ee; e++) red[warp][e] = acc[e];
    __syncthreads();
    if (threadIdx.x == 0) {
        float l[Ee];
        for (int e = 0; e < Ee; e++) {
            float ssum = 0.f;
            for (int w = 0; w < 8; w++) ssum += red[w][e];
            l[e] = ssum;
        }
        int i1 = 0;
        for (int e = 1; e < Ee; e++) if (l[e] > l[i1]) i1 = e;
        int i2 = -1;
        for (int e = 0; e < Ee; e++) if (e != i1 && (i2 < 0 || l[e] > l[i2])) i2 = e;
        float w1 = 1.f / (1.f + __expf(l[i2] - l[i1]));
        g_rwflat[2*t]   = w1;
        g_rwflat[2*t+1] = 1.f - w1;
        int p1 = atomicAdd(&g_ecount[i1], 1); g_elist[i1*Tt + p1] = 2*t;
        int p2 = atomicAdd(&g_ecount[i2], 1); g_elist[i2*Tt + p2] = 2*t + 1;
    }
}

// ---------------- elementwise ----------------
__global__ void swiglu_moe_kernel(float* __restrict__ gb, const float* __restrict__ ub)
{
    int idx = blockIdx.x*256 + threadIdx.x;
    int e = idx >> 21;
    int r = (idx >> 9) & 4095;
    if (r >= g_ecount[e]) return;
    float g = gb[idx], u = ub[idx];
    gb[idx] = g * u / (1.f + __expf(-g));
}

__global__ void swiglu_shared_kernel(const float* __restrict__ shg, float* __restrict__ sha)
{
    int idx = blockIdx.x*256 + threadIdx.x;
    int t = idx >> 10;
    int i = idx & 1023;
    float a = shg[(size_t)t*2*ISH + i];
    float b = shg[(size_t)t*2*ISH + ISH + i];
    sha[idx] = a * b / (1.f + __expf(-a));
}

__global__ void combine_kernel(const float* __restrict__ hid,
                               const float* __restrict__ yd,
                               const float* __restrict__ shr,
                               float* __restrict__ out)
{
    int idx = blockIdx.x*256 + threadIdx.x;
    int t = idx / Hh;
    int c = idx - t*Hh;
    float mo = g_rwflat[2*t]   * yd[(size_t)(2*t)*Hh + c]
             + g_rwflat[2*t+1] * yd[(size_t)(2*t+1)*Hh + c];
    out[idx] = hid[idx] + RESMf * (mo + shr[idx]);
}

// ---------------- launch ----------------
extern "C" void kernel_launch(void* const* d_in, const int* in_sizes, int n_in,
                              void* d_out, int out_size)
{
    const float* hidden    = (const float*)d_in[0];
    const int*   pos       = (const int*)  d_in[1];
    const float* cosb      = (const float*)d_in[2];
    const float* sinb      = (const float*)d_in[3];
    const float* ln1       = (const float*)d_in[4];
    const float* ln2       = (const float*)d_in[5];
    const float* wq        = (const float*)d_in[6];
    const float* wk        = (const float*)d_in[7];
    const float* wv        = (const float*)d_in[8];
    const float* wo        = (const float*)d_in[9];
    const float* router_w  = (const float*)d_in[10];
    const float* w_gate    = (const float*)d_in[11];
    const float* w_up      = (const float*)d_in[12];
    const float* w_down    = (const float*)d_in[13];
    const float* shared_in = (const float*)d_in[14];
    const float* shared_ot = (const float*)d_in[15];
    float* out = (float*)d_out;

    float *p_xnorm, *p_q, *p_k, *p_v, *p_attn, *p_hidden, *p_x2;
    float *p_shg, *p_shh, *p_shared, *p_gbuf, *p_ubuf, *p_ydown;
    u16 *pb_wq,*pb_wk,*pb_wv,*pb_wo,*pb_shin,*pb_shout,*pb_wg,*pb_wu,*pb_wd;
    cudaGetSymbolAddress((void**)&p_xnorm,  g_xnorm);
    cudaGetSymbolAddress((void**)&p_q,      g_q);
    cudaGetSymbolAddress((void**)&p_k,      g_k);
    cudaGetSymbolAddress((void**)&p_v,      g_v);
    cudaGetSymbolAddress((void**)&p_attn,   g_attn);
    cudaGetSymbolAddress((void**)&p_hidden, g_hidden);
    cudaGetSymbolAddress((void**)&p_x2,     g_x2);
    cudaGetSymbolAddress((void**)&p_shg,    g_shgate);
    cudaGetSymbolAddress((void**)&p_shh,    g_shh);
    cudaGetSymbolAddress((void**)&p_shared, g_shared);
    cudaGetSymbolAddress((void**)&p_gbuf,   g_gbuf);
    cudaGetSymbolAddress((void**)&p_ubuf,   g_ubuf);
    cudaGetSymbolAddress((void**)&p_ydown,  g_ydown);
    cudaGetSymbolAddress((void**)&pb_wq,    b_wq);
    cudaGetSymbolAddress((void**)&pb_wk,    b_wk);
    cudaGetSymbolAddress((void**)&pb_wv,    b_wv);
    cudaGetSymbolAddress((void**)&pb_wo,    b_wo);
    cudaGetSymbolAddress((void**)&pb_shin,  b_shin);
    cudaGetSymbolAddress((void**)&pb_shout, b_shout);
    cudaGetSymbolAddress((void**)&pb_wg,    b_wg);
    cudaGetSymbolAddress((void**)&pb_wu,    b_wu);
    cudaGetSymbolAddress((void**)&pb_wd,    b_wd);

    cudaFuncSetAttribute(tc_gemm,     cudaFuncAttributeMaxDynamicSharedMemorySize, SMEM_BYTES);
    cudaFuncSetAttribute(tc_qkv,      cudaFuncAttributeMaxDynamicSharedMemorySize, SMEM_BYTES);
    cudaFuncSetAttribute(tc_moe_gu,   cudaFuncAttributeMaxDynamicSharedMemorySize, SMEM_BYTES);
    cudaFuncSetAttribute(tc_moe_down, cudaFuncAttributeMaxDynamicSharedMemorySize, SMEM_BYTES);
    cudaFuncSetAttribute(tc_attn,     cudaFuncAttributeMaxDynamicSharedMemorySize, ATTN_SMEM);

    // ---- weight conversion (once per launch; graph-replayed) ----
    #define CV(src, dst, n) cvt_bf16<<<((n)/4 + 255)/256, 256>>>((src), (dst), (n)/4)
    CV(wq, pb_wq, Hh*Hh);
    CV(wk, pb_wk, NKVh*Dd*Hh);
    CV(wv, pb_wv, NKVh*Dd*Hh);
    CV(wo, pb_wo, Hh*Hh);
    CV(shared_in, pb_shin, 2*ISH*Hh);
    CV(shared_ot, pb_shout, Hh*ISH);
    CV(w_gate, pb_wg, Ee*IEXP*Hh);
    CV(w_up,   pb_wu, Ee*IEXP*Hh);
    CV(w_down, pb_wd, Ee*Hh*IEXP);
    #undef CV

    // ---- attention block ----
    rmsnorm_kernel<<<Tt, 256>>>(hidden, ln1, p_xnorm);
    tc_qkv<<<dim3(20,32), 256, SMEM_BYTES>>>(p_xnorm, pb_wq, pb_wk, pb_wv, p_q, p_k, p_v);
    rope_kernel<<<(Tt*NHq*64 + 255)/256, 256>>>(p_q, NHq, pos, cosb, sinb);
    rope_kernel<<<(Tt*NKVh*64 + 255)/256, 256>>>(p_k, NKVh, pos, cosb, sinb);
    tc_attn<<<dim3(Ss/64, NHq, Bb), 128, ATTN_SMEM>>>(p_q, p_k, p_v, p_attn);
    tc_gemm<<<dim3(12,32), 256, SMEM_BYTES>>>(p_attn, Hh, pb_wo, Hh, p_hidden, Hh, Hh, RESMf, hidden);

    // ---- MoE + shared MLP block ----
    rmsnorm_kernel<<<Tt, 256>>>(p_hidden, ln2, p_x2);
    zero_counts<<<1, 32>>>();
    router_kernel<<<Tt, 256>>>(p_x2, router_w);
    tc_gemm<<<dim3(16,32), 256, SMEM_BYTES>>>(p_x2, Hh, pb_shin, Hh, p_shg, 2*ISH, Hh, 1.f, nullptr);
    tc_moe_gu<<<dim3(8,32,Ee), 256, SMEM_BYTES>>>(p_x2, pb_wg, pb_wu, p_gbuf, p_ubuf);
    swiglu_moe_kernel<<<(Ee*Tt*IEXP)/256, 256>>>(p_gbuf, p_ubuf);
    tc_moe_down<<<dim3(12,32,Ee), 256, SMEM_BYTES>>>(p_gbuf, pb_wd, p_ydown);
    swiglu_shared_kernel<<<(Tt*ISH)/256, 256>>>(p_shg, p_shh);
    tc_gemm<<<dim3(12,32), 256, SMEM_BYTES>>>(p_shh, ISH, pb_shout, ISH, p_shared, Hh, ISH, 1.f, nullptr);
    combine_kernel<<<(Tt*Hh)/256, 256>>>(p_hidden, p_ydown, p_shared, out);
}

// round 17
// speedup vs baseline: 1.4049x; 1.0786x over previous
#include <cuda_runtime.h>
#include <cstdint>

// ---------------- problem constants ----------------
#define Bb 2
#define Ss 2048
#define Hh 1536
#define NHq 12
#define NKVh 4
#define Dd 128
#define Tt (Bb*Ss)          // 4096
#define Ee 8
#define IEXP 512
#define ISH 1024
#define SCALEf 0.0078125f
#define RESMf 0.22f
#define EPSf 1e-6f

typedef unsigned short u16;

// ---------------- scratch ----------------
__device__ float g_xnorm [Tt*Hh];
__device__ float g_q     [Tt*Hh];
__device__ float g_k     [Tt*NKVh*Dd];
__device__ float g_v     [Tt*NKVh*Dd];
__device__ float g_attn  [Tt*Hh];
__device__ float g_hidden[Tt*Hh];
__device__ float g_x2    [Tt*Hh];
__device__ float g_shg   [Tt*ISH];      // a-half (compact)
__device__ float g_shh   [Tt*ISH];      // silu(a)*b
__device__ float g_shared[Tt*Hh];
__device__ float g_gbuf  [Ee*Tt*IEXP];  // gate, then silu(g)*u in place
__device__ float g_ydown [Tt*2*Hh];
__device__ int   g_elist [Ee*Tt];
__device__ int   g_ecount[Ee];
__device__ float g_rwflat[Tt*2];
// bf16 weight copies
__device__ u16 b_wq   [Hh*Hh];
__device__ u16 b_wk   [NKVh*Dd*Hh];
__device__ u16 b_wv   [NKVh*Dd*Hh];
__device__ u16 b_wo   [Hh*Hh];
__device__ u16 b_shin [2*ISH*Hh];
__device__ u16 b_shout[Hh*ISH];
__device__ u16 b_wg   [Ee*IEXP*Hh];
__device__ u16 b_wu   [Ee*IEXP*Hh];
__device__ u16 b_wd   [Ee*Hh*IEXP];

// ---------------- helpers ----------------
__device__ __forceinline__ unsigned pk(float lo, float hi)
{
    unsigned r;
    asm("cvt.rn.bf16x2.f32 %0, %1, %2;" : "=r"(r) : "f"(hi), "f"(lo));
    return r;
}

#define MMA_BF16(acc, a0,a1,a2,a3, b0,b1) \
    asm volatile( \
        "mma.sync.aligned.m16n8k16.row.col.f32.bf16.bf16.f32 " \
        "{%0,%1,%2,%3}, {%4,%5,%6,%7}, {%8,%9}, {%0,%1,%2,%3};" \
        : "+f"((acc)[0]), "+f"((acc)[1]), "+f"((acc)[2]), "+f"((acc)[3]) \
        : "r"(a0), "r"(a1), "r"(a2), "r"(a3), "r"(b0), "r"(b1))

__device__ __forceinline__ void cpa16(void* smem, const void* gmem)
{
    unsigned sa = (unsigned)__cvta_generic_to_shared(smem);
    asm volatile("cp.async.cg.shared.global [%0], [%1], 16;" :: "r"(sa), "l"(gmem));
}
#define CP_COMMIT() asm volatile("cp.async.commit_group;")
#define CP_WAIT0()  asm volatile("cp.async.wait_group 0;")

// ---------------- weight conversion ----------------
__global__ void cvt_bf16(const float* __restrict__ src, u16* __restrict__ dst, int n4)
{
    int i = blockIdx.x*256 + threadIdx.x;
    if (i >= n4) return;
    float4 v = ((const float4*)src)[i];
    uint2 o; o.x = pk(v.x, v.y); o.y = pk(v.z, v.w);
    ((uint2*)dst)[i] = o;
}

// ---------------- GEMM core ----------------
struct SmemT {
    u16 As[2][128][40];
    u16 Bs[2][128][40];
};
#define SMEM_BYTES ((int)sizeof(SmemT))   // 40960

__device__ __forceinline__ void mma_compute(
    const u16 (&A)[128][40], const u16 (&B)[128][40],
    int lane, int wm, int wn, float (&acc)[2][8][4])
{
    const int g = lane >> 2, t2 = (lane & 3)*2;
    #pragma unroll
    for (int kk = 0; kk < 2; kk++) {
        const int kb = kk*16;
        unsigned af[2][4];
        #pragma unroll
        for (int mt = 0; mt < 2; mt++) {
            int ar = wm*32 + mt*16 + g;
            af[mt][0] = *(const unsigned*)&A[ar  ][kb + t2];
            af[mt][1] = *(const unsigned*)&A[ar+8][kb + t2];
            af[mt][2] = *(const unsigned*)&A[ar  ][kb + t2 + 8];
            af[mt][3] = *(const unsigned*)&A[ar+8][kb + t2 + 8];
        }
        #pragma unroll
        for (int nt = 0; nt < 8; nt++) {
            int br = wn*64 + nt*8 + g;
            unsigned b0 = *(const unsigned*)&B[br][kb + t2];
            unsigned b1 = *(const unsigned*)&B[br][kb + t2 + 8];
            #pragma unroll
            for (int mt = 0; mt < 2; mt++)
                MMA_BF16(acc[mt][nt], af[mt][0],af[mt][1],af[mt][2],af[mt][3], b0,b1);
        }
    }
}

// double-buffered K loop: A fp32 via registers (+cvt), B bf16 via cp.async
__device__ __forceinline__ void mix_db(
    SmemT& S, const float* ag, const u16* bg,
    int row, int c0off, int K,
    int lane, int wm, int wn, float (&acc)[2][8][4])
{
    float4 a0v = ag ? *(const float4*)(ag)      : make_float4(0,0,0,0);
    float4 a1v = ag ? *(const float4*)(ag + 4)  : make_float4(0,0,0,0);
    float4 a2v = ag ? *(const float4*)(ag + 8)  : make_float4(0,0,0,0);
    float4 a3v = ag ? *(const float4*)(ag + 12) : make_float4(0,0,0,0);
    cpa16(&S.Bs[0][row][c0off],     bg);
    cpa16(&S.Bs[0][row][c0off + 8], bg + 8);
    uint4 ap0, ap1;
    ap0.x = pk(a0v.x, a0v.y); ap0.y = pk(a0v.z, a0v.w);
    ap0.z = pk(a1v.x, a1v.y); ap0.w = pk(a1v.z, a1v.w);
    ap1.x = pk(a2v.x, a2v.y); ap1.y = pk(a2v.z, a2v.w);
    ap1.z = pk(a3v.x, a3v.y); ap1.w = pk(a3v.z, a3v.w);
    *(uint4*)&S.As[0][row][c0off]     = ap0;
    *(uint4*)&S.As[0][row][c0off + 8] = ap1;
    CP_COMMIT(); CP_WAIT0();
    __syncthreads();

    int cur = 0;
    for (int k0 = 32; k0 < K; k0 += 32) {
        a0v = ag ? *(const float4*)(ag + k0)      : make_float4(0,0,0,0);
        a1v = ag ? *(const float4*)(ag + k0 + 4)  : make_float4(0,0,0,0);
        a2v = ag ? *(const float4*)(ag + k0 + 8)  : make_float4(0,0,0,0);
        a3v = ag ? *(const float4*)(ag + k0 + 12) : make_float4(0,0,0,0);
        int nxt = cur ^ 1;
        cpa16(&S.Bs[nxt][row][c0off],     bg + k0);
        cpa16(&S.Bs[nxt][row][c0off + 8], bg + k0 + 8);
        mma_compute(S.As[cur], S.Bs[cur], lane, wm, wn, acc);
        ap0.x = pk(a0v.x, a0v.y); ap0.y = pk(a0v.z, a0v.w);
        ap0.z = pk(a1v.x, a1v.y); ap0.w = pk(a1v.z, a1v.w);
        ap1.x = pk(a2v.x, a2v.y); ap1.y = pk(a2v.z, a2v.w);
        ap1.z = pk(a3v.x, a3v.y); ap1.w = pk(a3v.z, a3v.w);
        *(uint4*)&S.As[nxt][row][c0off]     = ap0;
        *(uint4*)&S.As[nxt][row][c0off + 8] = ap1;
        CP_COMMIT(); CP_WAIT0();
        __syncthreads();
        cur = nxt;
    }
    mma_compute(S.As[cur], S.Bs[cur], lane, wm, wn, acc);
}

// ---------------- generic TN GEMM (fp32 out, +res/alpha) ----------------
__global__ void __launch_bounds__(256, 2) tc_gemm(
    const float* __restrict__ A, int lda,
    const u16* __restrict__ B, int ldb,
    float* __restrict__ C, int ldc,
    int K, float alpha, const float* __restrict__ res)
{
    extern __shared__ char smemraw[];
    SmemT& S = *reinterpret_cast<SmemT*>(smemraw);
    const int tid = threadIdx.x, lane = tid & 31, warp = tid >> 5;
    const int wm = warp & 3, wn = warp >> 2;
    const int m0 = blockIdx.y*128, n0 = blockIdx.x*128;
    const int row = tid >> 1, c0off = (tid & 1)*16;
    const float* ag = A + (size_t)(m0+row)*lda + c0off;
    const u16*   bg = B + (size_t)(n0+row)*ldb + c0off;

    float acc[2][8][4];
    #pragma unroll
    for (int i=0;i<2;i++) for (int j=0;j<8;j++) for (int c=0;c<4;c++) acc[i][j][c]=0.f;

    mix_db(S, ag, bg, row, c0off, K, lane, wm, wn, acc);

    const int g = lane >> 2, t = lane & 3;
    #pragma unroll
    for (int mt = 0; mt < 2; mt++) {
        int gm = m0 + wm*32 + mt*16 + g;
        #pragma unroll
        for (int nt = 0; nt < 8; nt++) {
            int gn = n0 + wn*64 + nt*8 + t*2;
            float2 v0, v1;
            v0.x = alpha*acc[mt][nt][0]; v0.y = alpha*acc[mt][nt][1];
            v1.x = alpha*acc[mt][nt][2]; v1.y = alpha*acc[mt][nt][3];
            if (res) {
                const float* r0 = res + (size_t)gm*ldc + gn;
                const float* r1 = res + (size_t)(gm+8)*ldc + gn;
                v0.x += r0[0]; v0.y += r0[1];
                v1.x += r1[0]; v1.y += r1[1];
            }
            *(float2*)(C + (size_t)gm*ldc + gn)     = v0;
            *(float2*)(C + (size_t)(gm+8)*ldc + gn) = v1;
        }
    }
}

// ---------------- TN GEMM with swiglu epilogue: C = silu(gate)*acc ----------------
__global__ void __launch_bounds__(256, 2) tc_gemm_swiglu(
    const float* __restrict__ A, int lda,
    const u16* __restrict__ B, int ldb,
    const float* __restrict__ gate,
    float* __restrict__ C, int ldc, int K)
{
    extern __shared__ char smemraw[];
    SmemT& S = *reinterpret_cast<SmemT*>(smemraw);
    const int tid = threadIdx.x, lane = tid & 31, warp = tid >> 5;
    const int wm = warp & 3, wn = warp >> 2;
    const int m0 = blockIdx.y*128, n0 = blockIdx.x*128;
    const int row = tid >> 1, c0off = (tid & 1)*16;
    const float* ag = A + (size_t)(m0+row)*lda + c0off;
    const u16*   bg = B + (size_t)(n0+row)*ldb + c0off;

    float acc[2][8][4];
    #pragma unroll
    for (int i=0;i<2;i++) for (int j=0;j<8;j++) for (int c=0;c<4;c++) acc[i][j][c]=0.f;

    mix_db(S, ag, bg, row, c0off, K, lane, wm, wn, acc);

    const int g = lane >> 2, t = lane & 3;
    #pragma unroll
    for (int mt = 0; mt < 2; mt++) {
        int gm = m0 + wm*32 + mt*16 + g;
        #pragma unroll
        for (int nt = 0; nt < 8; nt++) {
            int gn = n0 + wn*64 + nt*8 + t*2;
            float2 g0 = *(const float2*)(gate + (size_t)gm*ldc + gn);
            float2 g1 = *(const float2*)(gate + (size_t)(gm+8)*ldc + gn);
            float2 v0, v1;
            v0.x = g0.x*acc[mt][nt][0] / (1.f + __expf(-g0.x));
            v0.y = g0.y*acc[mt][nt][1] / (1.f + __expf(-g0.y));
            v1.x = g1.x*acc[mt][nt][2] / (1.f + __expf(-g1.x));
            v1.y = g1.y*acc[mt][nt][3] / (1.f + __expf(-g1.y));
            *(float2*)(C + (size_t)gm*ldc + gn)     = v0;
            *(float2*)(C + (size_t)(gm+8)*ldc + gn) = v1;
        }
    }
}

// ---------------- fused QKV ----------------
__global__ void __launch_bounds__(256, 2) tc_qkv(
    const float* __restrict__ A,
    const u16* __restrict__ wq, const u16* __restrict__ wk, const u16* __restrict__ wv,
    float* __restrict__ q, float* __restrict__ k, float* __restrict__ v)
{
    extern __shared__ char smemraw[];
    SmemT& S = *reinterpret_cast<SmemT*>(smemraw);
    const int bx = blockIdx.x;
    const u16* B; float* C; int ldc, n0;
    if (bx < 12)      { B = wq; C = q; ldc = Hh;      n0 = bx*128; }
    else if (bx < 16) { B = wk; C = k; ldc = NKVh*Dd; n0 = (bx-12)*128; }
    else              { B = wv; C = v; ldc = NKVh*Dd; n0 = (bx-16)*128; }

    const int tid = threadIdx.x, lane = tid & 31, warp = tid >> 5;
    const int wm = warp & 3, wn = warp >> 2;
    const int m0 = blockIdx.y*128;
    const int row = tid >> 1, c0off = (tid & 1)*16;
    const float* ag = A + (size_t)(m0+row)*Hh + c0off;
    const u16*   bg = B + (size_t)(n0+row)*Hh + c0off;

    float acc[2][8][4];
    #pragma unroll
    for (int i=0;i<2;i++) for (int j=0;j<8;j++) for (int c=0;c<4;c++) acc[i][j][c]=0.f;

    mix_db(S, ag, bg, row, c0off, Hh, lane, wm, wn, acc);

    const int g = lane >> 2, t = lane & 3;
    #pragma unroll
    for (int mt = 0; mt < 2; mt++) {
        int gm = m0 + wm*32 + mt*16 + g;
        #pragma unroll
        for (int nt = 0; nt < 8; nt++) {
            int gn = n0 + wn*64 + nt*8 + t*2;
            float2 v0, v1;
            v0.x = acc[mt][nt][0]; v0.y = acc[mt][nt][1];
            v1.x = acc[mt][nt][2]; v1.y = acc[mt][nt][3];
            *(float2*)(C + (size_t)gm*ldc + gn)     = v0;
            *(float2*)(C + (size_t)(gm+8)*ldc + gn) = v1;
        }
    }
}

// ---------------- MoE gate GEMM (gathered rows) -> gbuf ----------------
__global__ void __launch_bounds__(256, 2) tc_moe_gate(
    const float* __restrict__ X,
    const u16* __restrict__ w_gate,
    float* __restrict__ gbuf)
{
    const int e = blockIdx.z;
    const int count = g_ecount[e];
    const int m0 = blockIdx.y*128;
    if (m0 >= count) return;
    extern __shared__ char smemraw[];
    SmemT& S = *reinterpret_cast<SmemT*>(smemraw);
    __shared__ int rowmap[128];

    const u16* B = w_gate + (size_t)e*IEXP*Hh;
    const int n0 = blockIdx.x*128;
    const int tid = threadIdx.x, lane = tid & 31, warp = tid >> 5;
    const int wm = warp & 3, wn = warp >> 2;
    const int row = tid >> 1, c0off = (tid & 1)*16;
    if (tid < 128) {
        int r = m0 + tid;
        rowmap[tid] = (r < count) ? (g_elist[e*Tt + r] >> 1) : -1;
    }
    __syncthreads();
    int src = rowmap[row];
    const float* ag = (src >= 0) ? X + (size_t)src*Hh + c0off : nullptr;
    const u16*   bg = B + (size_t)(n0+row)*Hh + c0off;

    float acc[2][8][4];
    #pragma unroll
    for (int i=0;i<2;i++) for (int j=0;j<8;j++) for (int c=0;c<4;c++) acc[i][j][c]=0.f;

    mix_db(S, ag, bg, row, c0off, Hh, lane, wm, wn, acc);

    const int g = lane >> 2, t = lane & 3;
    #pragma unroll
    for (int mt = 0; mt < 2; mt++) {
        int r0 = m0 + wm*32 + mt*16 + g;
        #pragma unroll
        for (int nt = 0; nt < 8; nt++) {
            int gn = n0 + wn*64 + nt*8 + t*2;
            if (r0 < count) {
                float2 v; v.x = acc[mt][nt][0]; v.y = acc[mt][nt][1];
                *(float2*)(gbuf + ((size_t)e*Tt + r0)*IEXP + gn) = v;
            }
            if (r0+8 < count) {
                float2 v; v.x = acc[mt][nt][2]; v.y = acc[mt][nt][3];
                *(float2*)(gbuf + ((size_t)e*Tt + r0+8)*IEXP + gn) = v;
            }
        }
    }
}

// ---------------- MoE up GEMM + fused swiglu: gbuf = silu(gbuf)*u ----------------
__global__ void __launch_bounds__(256, 2) tc_moe_up(
    const float* __restrict__ X,
    const u16* __restrict__ w_up,
    float* __restrict__ gbuf)
{
    const int e = blockIdx.z;
    const int count = g_ecount[e];
    const int m0 = blockIdx.y*128;
    if (m0 >= count) return;
    extern __shared__ char smemraw[];
    SmemT& S = *reinterpret_cast<SmemT*>(smemraw);
    __shared__ int rowmap[128];

    const u16* B = w_up + (size_t)e*IEXP*Hh;
    const int n0 = blockIdx.x*128;
    const int tid = threadIdx.x, lane = tid & 31, warp = tid >> 5;
    const int wm = warp & 3, wn = warp >> 2;
    const int row = tid >> 1, c0off = (tid & 1)*16;
    if (tid < 128) {
        int r = m0 + tid;
        rowmap[tid] = (r < count) ? (g_elist[e*Tt + r] >> 1) : -1;
    }
    __syncthreads();
    int src = rowmap[row];
    const float* ag = (src >= 0) ? X + (size_t)src*Hh + c0off : nullptr;
    const u16*   bg = B + (size_t)(n0+row)*Hh + c0off;

    float acc[2][8][4];
    #pragma unroll
    for (int i=0;i<2;i++) for (int j=0;j<8;j++) for (int c=0;c<4;c++) acc[i][j][c]=0.f;

    mix_db(S, ag, bg, row, c0off, Hh, lane, wm, wn, acc);

    const int g = lane >> 2, t = lane & 3;
    #pragma unroll
    for (int mt = 0; mt < 2; mt++) {
        int r0 = m0 + wm*32 + mt*16 + g;
        #pragma unroll
        for (int nt = 0; nt < 8; nt++) {
            int gn = n0 + wn*64 + nt*8 + t*2;
            if (r0 < count) {
                size_t off = ((size_t)e*Tt + r0)*IEXP + gn;
                float2 gv = *(const float2*)(gbuf + off);
                float2 v;
                v.x = gv.x*acc[mt][nt][0] / (1.f + __expf(-gv.x));
                v.y = gv.y*acc[mt][nt][1] / (1.f + __expf(-gv.y));
                *(float2*)(gbuf + off) = v;
            }
            if (r0+8 < count) {
                size_t off = ((size_t)e*Tt + r0+8)*IEXP + gn;
                float2 gv = *(const float2*)(gbuf + off);
                float2 v;
                v.x = gv.x*acc[mt][nt][2] / (1.f + __expf(-gv.x));
                v.y = gv.y*acc[mt][nt][3] / (1.f + __expf(-gv.y));
                *(float2*)(gbuf + off) = v;
            }
        }
    }
}

// ---------------- MoE down (scatter rows) ----------------
__global__ void __launch_bounds__(256, 2) tc_moe_down(
    const float* __restrict__ Gact,
    const u16* __restrict__ w_down,
    float* __restrict__ ydown)
{
    const int e = blockIdx.z;
    const int count = g_ecount[e];
    const int m0 = blockIdx.y*128;
    if (m0 >= count) return;
    extern __shared__ char smemraw[];
    SmemT& S = *reinterpret_cast<SmemT*>(smemraw);

    const u16* B = w_down + (size_t)e*Hh*IEXP;
    const int n0 = blockIdx.x*128;
    const int tid = threadIdx.x, lane = tid & 31, warp = tid >> 5;
    const int wm = warp & 3, wn = warp >> 2;
    const int row = tid >> 1, c0off = (tid & 1)*16;
    const float* ag = Gact + ((size_t)e*Tt + m0 + row)*IEXP + c0off;
    const u16*   bg = B + (size_t)(n0+row)*IEXP + c0off;

    float acc[2][8][4];
    #pragma unroll
    for (int i=0;i<2;i++) for (int j=0;j<8;j++) for (int c=0;c<4;c++) acc[i][j][c]=0.f;

    mix_db(S, ag, bg, row, c0off, IEXP, lane, wm, wn, acc);

    const int* lst = g_elist + e*Tt;
    const int g = lane >> 2, t = lane & 3;
    #pragma unroll
    for (int mt = 0; mt < 2; mt++) {
        int r0 = m0 + wm*32 + mt*16 + g;
        #pragma unroll
        for (int nt = 0; nt < 8; nt++) {
            int gn = n0 + wn*64 + nt*8 + t*2;
            if (r0 < count) {
                float2 v; v.x = acc[mt][nt][0]; v.y = acc[mt][nt][1];
                *(float2*)(ydown + (size_t)lst[r0]*Hh + gn) = v;
            }
            if (r0+8 < count) {
                float2 v; v.x = acc[mt][nt][2]; v.y = acc[mt][nt][3];
                *(float2*)(ydown + (size_t)lst[r0+8]*Hh + gn) = v;
            }
        }
    }
}

// ---------------- bf16 flash attention (proven round-14 version) ----------------
struct AttnSmem {
    u16 Qs[64][136];
    char kvbuf[18432];
    u16 Ps[64][72];
};
#define ATTN_SMEM ((int)sizeof(AttnSmem))  // 45056

__global__ void __launch_bounds__(128, 2) tc_attn(
    const float* __restrict__ Q, const float* __restrict__ Kg,
    const float* __restrict__ Vg, float* __restrict__ O)
{
    extern __shared__ char sraw[];
    AttnSmem& S = *reinterpret_cast<AttnSmem*>(sraw);
    u16 (*Ks)[136]      = reinterpret_cast<u16 (*)[136]>(S.kvbuf);
    unsigned (*VP)[36]  = reinterpret_cast<unsigned (*)[36]>(S.kvbuf);

    const int qt = blockIdx.x, h = blockIdx.y, b = blockIdx.z;
    const int kvh = h / (NHq/NKVh);
    const int tid = threadIdx.x, lane = tid & 31, warp = tid >> 5;
    const int g = lane >> 2, t = lane & 3, t2 = t*2;
    const int tq0 = b*Ss + qt*64;
    const int rA = warp*16 + g;

    #pragma unroll
    for (int i = 0; i < 16; i++) {
        int v = tid + i*128;
        int r = v >> 5, dq = (v & 31) << 2;
        float4 qv = *(const float4*)(Q + (size_t)(tq0+r)*Hh + h*Dd + dq);
        *(unsigned*)&S.Qs[r][dq]   = pk(qv.x*SCALEf, qv.y*SCALEf);
        *(unsigned*)&S.Qs[r][dq+2] = pk(qv.z*SCALEf, qv.w*SCALEf);
    }

    float o[16][4];
    #pragma unroll
    for (int i = 0; i < 16; i++)
        #pragma unroll
        for (int c = 0; c < 4; c++) o[i][c] = 0.f;
    float m0v = -1e30f, m1v = -1e30f, l0 = 0.f, l1 = 0.f;

    for (int kt = 0; kt <= qt; kt++) {
        const int tk0 = b*Ss + kt*64;
        __syncthreads();
        #pragma unroll
        for (int i = 0; i < 16; i++) {
            int v = tid + i*128;
            int r = v >> 5, dq = (v & 31) << 2;
            float4 kv = *(const float4*)(Kg + (size_t)(tk0+r)*(NKVh*Dd) + kvh*Dd + dq);
            *(unsigned*)&Ks[r][dq]   = pk(kv.x, kv.y);
            *(unsigned*)&Ks[r][dq+2] = pk(kv.z, kv.w);
        }
        __syncthreads();

        float s[8][4];
        #pragma unroll
        for (int nt = 0; nt < 8; nt++)
            #pragma unroll
            for (int c = 0; c < 4; c++) s[nt][c] = 0.f;
        #pragma unroll
        for (int kk = 0; kk < 8; kk++) {
            const int kb = kk*16;
            unsigned a0 = *(const unsigned*)&S.Qs[rA  ][kb + t2];
            unsigned a1 = *(const unsigned*)&S.Qs[rA+8][kb + t2];
            unsigned a2 = *(const unsigned*)&S.Qs[rA  ][kb + t2 + 8];
            unsigned a3 = *(const unsigned*)&S.Qs[rA+8][kb + t2 + 8];
            #pragma unroll
            for (int nt = 0; nt < 8; nt++) {
                unsigned b0 = *(const unsigned*)&Ks[nt*8+g][kb + t2];
                unsigned b1 = *(const unsigned*)&Ks[nt*8+g][kb + t2 + 8];
                MMA_BF16(s[nt], a0,a1,a2,a3, b0,b1);
            }
        }
        if (kt == qt) {
            #pragma unroll
            for (int nt = 0; nt < 8; nt++)
                #pragma unroll
                for (int j = 0; j < 2; j++) {
                    int col = nt*8 + t2 + j;
                    if (col > rA)   s[nt][j]   = -1e30f;
                    if (col > rA+8) s[nt][2+j] = -1e30f;
                }
        }
        float mx0 = -1e30f, mx1 = -1e30f;
        #pragma unroll
        for (int nt = 0; nt < 8; nt++) {
            mx0 = fmaxf(mx0, fmaxf(s[nt][0], s[nt][1]));
            mx1 = fmaxf(mx1, fmaxf(s[nt][2], s[nt][3]));
        }
        mx0 = fmaxf(mx0, __shfl_xor_sync(0xffffffffu, mx0, 1));
        mx0 = fmaxf(mx0, __shfl_xor_sync(0xffffffffu, mx0, 2));
        mx1 = fmaxf(mx1, __shfl_xor_sync(0xffffffffu, mx1, 1));
        mx1 = fmaxf(mx1, __shfl_xor_sync(0xffffffffu, mx1, 2));
        float mn0 = fmaxf(m0v, mx0), mn1 = fmaxf(m1v, mx1);
        float sc0 = __expf(m0v - mn0), sc1 = __expf(m1v - mn1);
        float sum0 = 0.f, sum1 = 0.f;
        #pragma unroll
        for (int nt = 0; nt < 8; nt++) {
            float p0 = __expf(s[nt][0] - mn0);
            float p1 = __expf(s[nt][1] - mn0);
            float p2 = __expf(s[nt][2] - mn1);
            float p3 = __expf(s[nt][3] - mn1);
            sum0 += p0 + p1; sum1 += p2 + p3;
            int c = nt*8 + t2;
            *(unsigned*)&S.Ps[rA  ][c] = pk(p0, p1);
            *(unsigned*)&S.Ps[rA+8][c] = pk(p2, p3);
        }
        sum0 += __shfl_xor_sync(0xffffffffu, sum0, 1);
        sum0 += __shfl_xor_sync(0xffffffffu, sum0, 2);
        sum1 += __shfl_xor_sync(0xffffffffu, sum1, 1);
        sum1 += __shfl_xor_sync(0xffffffffu, sum1, 2);
        l0 = l0*sc0 + sum0; l1 = l1*sc1 + sum1;
        m0v = mn0; m1v = mn1;
        #pragma unroll
        for (int nt = 0; nt < 16; nt++) {
            o[nt][0] *= sc0; o[nt][1] *= sc0;
            o[nt][2] *= sc1; o[nt][3] *= sc1;
        }
        __syncthreads();
        #pragma unroll
        for (int i = 0; i < 16; i++) {
            int idx = tid + i*128;
            int p   = idx >> 6;
            int d2  = (idx & 63) << 1;
            const float* vb = Vg + (size_t)(tk0 + 2*p)*(NKVh*Dd) + kvh*Dd + d2;
            float2 r0 = *(const float2*)(vb);
            float2 r1 = *(const float2*)(vb + NKVh*Dd);
            VP[d2  ][p] = pk(r0.x, r1.x);
            VP[d2+1][p] = pk(r0.y, r1.y);
        }
        __syncthreads();
        #pragma unroll
        for (int kk = 0; kk < 4; kk++) {
            const int kb = kk*16, kw = kk*8;
            unsigned a0 = *(const unsigned*)&S.Ps[rA  ][kb + t2];
            unsigned a1 = *(const unsigned*)&S.Ps[rA+8][kb + t2];
            unsigned a2 = *(const unsigned*)&S.Ps[rA  ][kb + t2 + 8];
            unsigned a3 = *(const unsigned*)&S.Ps[rA+8][kb + t2 + 8];
            #pragma unroll
            for (int nt = 0; nt < 16; nt++) {
                unsigned b0 = VP[nt*8+g][kw + t];
                unsigned b1 = VP[nt*8+g][kw + t + 4];
                MMA_BF16(o[nt], a0,a1,a2,a3, b0,b1);
            }
        }
    }

    float inv0 = 1.0f / l0, inv1 = 1.0f / l1;
    #pragma unroll
    for (int nt = 0; nt < 16; nt++) {
        int col = nt*8 + t2;
        float2 v0, v1;
        v0.x = o[nt][0]*inv0; v0.y = o[nt][1]*inv0;
        v1.x = o[nt][2]*inv1; v1.y = o[nt][3]*inv1;
        *(float2*)(O + (size_t)(tq0+rA)*Hh   + h*Dd + col) = v0;
        *(float2*)(O + (size_t)(tq0+rA+8)*Hh + h*Dd + col) = v1;
    }
}

// ---------------- rmsnorm ----------------
__global__ __launch_bounds__(256) void rmsnorm_kernel(
    const float* __restrict__ x, const float* __restrict__ w, float* __restrict__ y)
{
    int t = blockIdx.x;
    const float* xr = x + (size_t)t*Hh;
    float s = 0.f;
    for (int i = threadIdx.x; i < Hh; i += 256) { float v = xr[i]; s += v*v; }
    #pragma unroll
    for (int o = 16; o > 0; o >>= 1) s += __shfl_xor_sync(0xffffffffu, s, o);
    __shared__ float red[8];
    if ((threadIdx.x & 31) == 0) red[threadIdx.x >> 5] = s;
    __syncthreads();
    float tot = 0.f;
    #pragma unroll
    for (int wv = 0; wv < 8; wv++) tot += red[wv];
    float inv = rsqrtf(tot * (1.0f/(float)Hh) + EPSf);
    float* yr = y + (size_t)t*Hh;
    for (int i = threadIdx.x; i < Hh; i += 256) yr[i] = w[i]*xr[i]*inv;
}

// ---------------- RoPE ----------------
__global__ void rope_kernel(float* __restrict__ a, int nheads,
                            const int* __restrict__ pos_ids,
                            const float* __restrict__ cosb,
                            const float* __restrict__ sinb)
{
    int idx = blockIdx.x*256 + threadIdx.x;
    int total = Tt * nheads * 64;
    if (idx >= total) return;
    int dd = idx & 63;
    int hh = (idx >> 6) % nheads;
    int t  = idx / (64*nheads);
    int pos = pos_ids[t] & 4095;
    float c1 = cosb[pos*Dd + dd],      s1 = sinb[pos*Dd + dd];
    float c2 = cosb[pos*Dd + dd + 64], s2 = sinb[pos*Dd + dd + 64];
    float* base = a + (size_t)t*(nheads*Dd) + hh*Dd;
    float x1 = base[dd], x2 = base[dd+64];
    base[dd]     = x1*c1 - x2*s1;
    base[dd+64]  = x2*c2 + x1*s2;
}

// ---------------- router ----------------
__global__ void zero_counts() { if (threadIdx.x < Ee) g_ecount[threadIdx.x] = 0; }

__global__ __launch_bounds__(256) void router_kernel(
    const float* __restrict__ x, const float* __restrict__ rw)
{
    int t = blockIdx.x;
    const float* xr = x + (size_t)t*Hh;
    float acc[Ee];
    #pragma unroll
    for (int e = 0; e < Ee; e++) acc[e] = 0.f;
    for (int hh = threadIdx.x; hh < Hh; hh += 256) {
        float xv = xr[hh];
        #pragma unroll
        for (int e = 0; e < Ee; e++) acc[e] += xv * rw[e*Hh + hh];
    }
    #pragma unroll
    for (int e = 0; e < Ee; e++)
        #pragma unroll
        for (int o = 16; o > 0; o >>= 1) acc[e] += __shfl_xor_sync(0xffffffffu, acc[e], o);
    __shared__ float red[8][Ee];
    int warp = threadIdx.x >> 5, lane = threadIdx.x & 31;
    if (lane == 0)
        for (int e = 0; e < Ee; e++) red[warp][e] = acc[e];
    __syncthreads();
    if (threadIdx.x == 0) {
        float l[Ee];
        for (int e = 0; e < Ee; e++) {
            float ssum = 0.f;
            for (int w = 0; w < 8; w++) ssum += red[w][e];
            l[e] = ssum;
        }
        int i1 = 0;
        for (int e = 1; e < Ee; e++) if (l[e] > l[i1]) i1 = e;
        int i2 = -1;
        for (int e = 0; e < Ee; e++) if (e != i1 && (i2 < 0 || l[e] > l[i2])) i2 = e;
        float w1 = 1.f / (1.f + __expf(l[i2] - l[i1]));
        g_rwflat[2*t]   = w1;
        g_rwflat[2*t+1] = 1.f - w1;
        int p1 = atomicAdd(&g_ecount[i1], 1); g_elist[i1*Tt + p1] = 2*t;
        int p2 = atomicAdd(&g_ecount[i2], 1); g_elist[i2*Tt + p2] = 2*t + 1;
    }
}

// ---------------- combine ----------------
__global__ void combine_kernel(const float* __restrict__ hid,
                               const float* __restrict__ yd,
                               const float* __restrict__ shr,
                               float* __restrict__ out)
{
    int idx = blockIdx.x*256 + threadIdx.x;
    int t = idx / Hh;
    int c = idx - t*Hh;
    float mo = g_rwflat[2*t]   * yd[(size_t)(2*t)*Hh + c]
             + g_rwflat[2*t+1] * yd[(size_t)(2*t+1)*Hh + c];
    out[idx] = hid[idx] + RESMf * (mo + shr[idx]);
}

// ---------------- launch ----------------
extern "C" void kernel_launch(void* const* d_in, const int* in_sizes, int n_in,
                              void* d_out, int out_size)
{
    const float* hidden    = (const float*)d_in[0];
    const int*   pos       = (const int*)  d_in[1];
    const float* cosb      = (const float*)d_in[2];
    const float* sinb      = (const float*)d_in[3];
    const float* ln1       = (const float*)d_in[4];
    const float* ln2       = (const float*)d_in[5];
    const float* wq        = (const float*)d_in[6];
    const float* wk        = (const float*)d_in[7];
    const float* wv        = (const float*)d_in[8];
    const float* wo        = (const float*)d_in[9];
    const float* router_w  = (const float*)d_in[10];
    const float* w_gate    = (const float*)d_in[11];
    const float* w_up      = (const float*)d_in[12];
    const float* w_down    = (const float*)d_in[13];
    const float* shared_in = (const float*)d_in[14];
    const float* shared_ot = (const float*)d_in[15];
    float* out = (float*)d_out;

    float *p_xnorm, *p_q, *p_k, *p_v, *p_attn, *p_hidden, *p_x2;
    float *p_shg, *p_shh, *p_shared, *p_gbuf, *p_ydown;
    u16 *pb_wq,*pb_wk,*pb_wv,*pb_wo,*pb_shin,*pb_shout,*pb_wg,*pb_wu,*pb_wd;
    cudaGetSymbolAddress((void**)&p_xnorm,  g_xnorm);
    cudaGetSymbolAddress((void**)&p_q,      g_q);
    cudaGetSymbolAddress((void**)&p_k,      g_k);
    cudaGetSymbolAddress((void**)&p_v,      g_v);
    cudaGetSymbolAddress((void**)&p_attn,   g_attn);
    cudaGetSymbolAddress((void**)&p_hidden, g_hidden);
    cudaGetSymbolAddress((void**)&p_x2,     g_x2);
    cudaGetSymbolAddress((void**)&p_shg,    g_shg);
    cudaGetSymbolAddress((void**)&p_shh,    g_shh);
    cudaGetSymbolAddress((void**)&p_shared, g_shared);
    cudaGetSymbolAddress((void**)&p_gbuf,   g_gbuf);
    cudaGetSymbolAddress((void**)&p_ydown,  g_ydown);
    cudaGetSymbolAddress((void**)&pb_wq,    b_wq);
    cudaGetSymbolAddress((void**)&pb_wk,    b_wk);
    cudaGetSymbolAddress((void**)&pb_wv,    b_wv);
    cudaGetSymbolAddress((void**)&pb_wo,    b_wo);
    cudaGetSymbolAddress((void**)&pb_shin,  b_shin);
    cudaGetSymbolAddress((void**)&pb_shout, b_shout);
    cudaGetSymbolAddress((void**)&pb_wg,    b_wg);
    cudaGetSymbolAddress((void**)&pb_wu,    b_wu);
    cudaGetSymbolAddress((void**)&pb_wd,    b_wd);

    cudaFuncSetAttribute(tc_gemm,        cudaFuncAttributeMaxDynamicSharedMemorySize, SMEM_BYTES);
    cudaFuncSetAttribute(tc_gemm_swiglu, cudaFuncAttributeMaxDynamicSharedMemorySize, SMEM_BYTES);
    cudaFuncSetAttribute(tc_qkv,         cudaFuncAttributeMaxDynamicSharedMemorySize, SMEM_BYTES);
    cudaFuncSetAttribute(tc_moe_gate,    cudaFuncAttributeMaxDynamicSharedMemorySize, SMEM_BYTES);
    cudaFuncSetAttribute(tc_moe_up,      cudaFuncAttributeMaxDynamicSharedMemorySize, SMEM_BYTES);
    cudaFuncSetAttribute(tc_moe_down,    cudaFuncAttributeMaxDynamicSharedMemorySize, SMEM_BYTES);
    cudaFuncSetAttribute(tc_attn,        cudaFuncAttributeMaxDynamicSharedMemorySize, ATTN_SMEM);

    // ---- weight conversion (once per launch; graph-replayed) ----
    #define CV(src, dst, n) cvt_bf16<<<((n)/4 + 255)/256, 256>>>((src), (dst), (n)/4)
    CV(wq, pb_wq, Hh*Hh);
    CV(wk, pb_wk, NKVh*Dd*Hh);
    CV(wv, pb_wv, NKVh*Dd*Hh);
    CV(wo, pb_wo, Hh*Hh);
    CV(shared_in, pb_shin, 2*ISH*Hh);
    CV(shared_ot, pb_shout, Hh*ISH);
    CV(w_gate, pb_wg, Ee*IEXP*Hh);
    CV(w_up,   pb_wu, Ee*IEXP*Hh);
    CV(w_down, pb_wd, Ee*Hh*IEXP);
    #undef CV

    // ---- attention block ----
    rmsnorm_kernel<<<Tt, 256>>>(hidden, ln1, p_xnorm);
    tc_qkv<<<dim3(20,32), 256, SMEM_BYTES>>>(p_xnorm, pb_wq, pb_wk, pb_wv, p_q, p_k, p_v);
    rope_kernel<<<(Tt*NHq*64 + 255)/256, 256>>>(p_q, NHq, pos, cosb, sinb);
    rope_kernel<<<(Tt*NKVh*64 + 255)/256, 256>>>(p_k, NKVh, pos, cosb, sinb);
    tc_attn<<<dim3(Ss/64, NHq, Bb), 128, ATTN_SMEM>>>(p_q, p_k, p_v, p_attn);
    tc_gemm<<<dim3(12,32), 256, SMEM_BYTES>>>(p_attn, Hh, pb_wo, Hh, p_hidden, Hh, Hh, RESMf, hidden);

    // ---- MoE + shared MLP block ----
    rmsnorm_kernel<<<Tt, 256>>>(p_hidden, ln2, p_x2);
    zero_counts<<<1, 32>>>();
    router_kernel<<<Tt, 256>>>(p_x2, router_w);
    // shared MLP: a-half GEMM, then b-half GEMM with fused swiglu
    tc_gemm<<<dim3(8,32), 256, SMEM_BYTES>>>(p_x2, Hh, pb_shin, Hh, p_shg, ISH, Hh, 1.f, nullptr);
    tc_gemm_swiglu<<<dim3(8,32), 256, SMEM_BYTES>>>(p_x2, Hh, pb_shin + (size_t)ISH*Hh, Hh, p_shg, p_shh, ISH, Hh);
    // MoE: gate GEMM, then up GEMM with fused swiglu into gbuf
    tc_moe_gate<<<dim3(4,32,Ee), 256, SMEM_BYTES>>>(p_x2, pb_wg, p_gbuf);
    tc_moe_up  <<<dim3(4,32,Ee), 256, SMEM_BYTES>>>(p_x2, pb_wu, p_gbuf);
    tc_moe_down<<<dim3(12,32,Ee), 256, SMEM_BYTES>>>(p_gbuf, pb_wd, p_ydown);
    tc_gemm<<<dim3(12,32), 256, SMEM_BYTES>>>(p_shh, ISH, pb_shout, ISH, p_shared, Hh, ISH, 1.f, nullptr);
    combine_kernel<<<(Tt*Hh)/256, 256>>>(p_hidden, p_ydown, p_shared, out);
}